// round 3
// baseline (speedup 1.0000x reference)
#include <cuda_runtime.h>
#include <cuda_bf16.h>
#include <math.h>
#include <stdint.h>

#define BATCH   256
#define SEQ     256
#define INPUT   128
#define HIDDEN  1024
#define ZS      1026
#define NG      4096          // 4*HIDDEN interleaved: col n' = 4*j + gate
#define KIN     1154
#define KP      1168          // padded K (73*16)
#define NITER   73
#define MHU     1.5f

// Activation column layout: [x(2) | pad(2) | u(128) | h(1024) | pad(12)]
// Double-buffered by step parity.
__device__ __align__(16) __nv_bfloat16 g_Whi[NG * KP];
__device__ __align__(16) __nv_bfloat16 g_Wlo[NG * KP];
__device__ __align__(16) float         g_bint[NG];
__device__ __align__(16) __nv_bfloat16 g_Ahi[2 * BATCH * KP];
__device__ __align__(16) __nv_bfloat16 g_Alo[2 * BATCH * KP];
__device__ __align__(16) float         g_c[BATCH * HIDDEN];
__device__ __align__(16) float         g_x[2 * BATCH * 2];
__device__ __align__(16) float4        g_part[2 * 4 * 64 * 32]; // [p][grp][row][nblk]
__device__ unsigned int                g_ctr[4];

__device__ __forceinline__ float sigf(float x) {
    return __fdividef(1.f, 1.f + __expf(-x));
}
__device__ __forceinline__ float tanhfast(float x) {
    return 2.f * sigf(2.f * x) - 1.f;
}
__device__ __forceinline__ void bf16split(float v, __nv_bfloat16* hi, __nv_bfloat16* lo) {
    __nv_bfloat16 h = __float2bfloat16(v);
    *hi = h;
    *lo = __float2bfloat16(v - __bfloat162float(h));
}
__device__ __forceinline__ void mma16816(float* c, const uint32_t* a, const uint32_t* b) {
    asm volatile(
        "mma.sync.aligned.m16n8k16.row.col.f32.bf16.bf16.f32 "
        "{%0,%1,%2,%3}, {%4,%5,%6,%7}, {%8,%9}, {%0,%1,%2,%3};"
        : "+f"(c[0]), "+f"(c[1]), "+f"(c[2]), "+f"(c[3])
        : "r"(a[0]), "r"(a[1]), "r"(a[2]), "r"(a[3]), "r"(b[0]), "r"(b[1]));
}
__device__ __forceinline__ void cpasync16(uint32_t dst, const void* src) {
    asm volatile("cp.async.cg.shared.global [%0], [%1], 16;" :: "r"(dst), "l"(src));
}

// ---------------------------------------------------------------------------
__global__ void repack(const float* __restrict__ WU_w, const float* __restrict__ WU_b) {
    int idx = blockIdx.x * blockDim.x + threadIdx.x;
    const int total = NG * KP;
    for (int i = idx; i < total; i += gridDim.x * blockDim.x) {
        int np = i / KP;
        int k  = i - np * KP;
        int j  = np >> 2;
        int g  = np & 3;
        int n  = g * HIDDEN + j;
        float v = 0.f;
        if (k < 2)                   v = WU_w[(size_t)n * KIN + k];
        else if (k >= 4 && k < 1156) v = WU_w[(size_t)n * KIN + (k - 2)];
        __nv_bfloat16 hi, lo;
        bf16split(v, &hi, &lo);
        g_Whi[i] = hi;
        g_Wlo[i] = lo;
    }
    if (idx < NG) {
        int j = idx >> 2, g = idx & 3;
        g_bint[idx] = WU_b[g * HIDDEN + j];
    }
}

__global__ void init_state(const float* __restrict__ z0,
                           const float* __restrict__ c_z0,
                           const float* __restrict__ rnn_input) {
    int b = blockIdx.x, tid = threadIdx.x;
    for (int k = tid; k < KP; k += 256) {
        float v = 0.f;
        if (k < 2)                     v = z0[b * ZS + k];
        else if (k >= 4 && k < 132)    v = rnn_input[(size_t)b * SEQ * INPUT + (k - 4)];
        else if (k >= 132 && k < 1156) v = z0[b * ZS + 2 + (k - 132)];
        __nv_bfloat16 hi, lo;
        bf16split(v, &hi, &lo);
        g_Ahi[b * KP + k] = hi;
        g_Alo[b * KP + k] = lo;
    }
    if (tid < 2) g_x[b * 2 + tid] = z0[b * ZS + tid];
    for (int j = tid; j < HIDDEN; j += 256)
        g_c[b * HIDDEN + j] = c_z0[b * ZS + 2 + j];
    if (b == 0 && tid < 4) g_ctr[tid] = 0u;
}

// ---------------------------------------------------------------------------
// Persistent kernel: 128 CTAs = 4 m-groups (64 batch rows) x 32 n-blocks
// (128 interleaved gate cols = 32 hidden units each). Per step: split-bf16
// mma GEMM + fused LSTM epilogue + group spin-barrier + replicated x-update.
// ---------------------------------------------------------------------------
// smem stage layout (bytes): Ahi[0,3072) Alo[3072,6144) Whi[6144,12288) Wlo[12288,18432)
#define STAGE_B 18432

__global__ void __launch_bounds__(256) persistent_rnn(
    const float* __restrict__ rnn_input, const float* __restrict__ tau,
    const float* __restrict__ alpha_w,   const float* __restrict__ alpha_b,
    const float* __restrict__ Whx_w,     const float* __restrict__ Whx_b,
    float* __restrict__ out)
{
    __shared__ __align__(16) unsigned char smbuf[2 * STAGE_B];
    __shared__ __align__(16) float4 partsm[64][4];

    const int tid  = threadIdx.x;
    const int grp  = blockIdx.x >> 5;
    const int nblk = blockIdx.x & 31;
    const int m0   = grp * 64;
    const int n0   = nblk * 128;
    const int lane = tid & 31, wid = tid >> 5;
    const int warp_m = wid >> 2, warp_n = wid & 3;
    const int r = lane >> 2, q = lane & 3;

    // staging assignments
    const int arow = (tid & 127) >> 1, acol8 = tid & 1;
    const int wrow = tid >> 1,         wcol8 = tid & 1;
    const bool aIsHi = tid < 128;

    const uint32_t smbase   = (uint32_t)__cvta_generic_to_shared(smbuf);
    const uint32_t a_dst_o  = (aIsHi ? 0u : 3072u) + arow * 48 + acol8 * 16;
    const uint32_t wh_dst_o = 6144u  + wrow * 48 + wcol8 * 16;
    const uint32_t wl_dst_o = 12288u + wrow * 48 + wcol8 * 16;

    const __nv_bfloat16* Whb = g_Whi + (size_t)(n0 + wrow) * KP + wcol8 * 8;
    const __nv_bfloat16* Wlb = g_Wlo + (size_t)(n0 + wrow) * KP + wcol8 * 8;

    unsigned int target = 0;

    for (int t = 0; t < SEQ; t++) {
        const int p = t & 1;
        const __nv_bfloat16* Abase =
            (aIsHi ? g_Ahi : g_Alo) + (size_t)p * BATCH * KP
            + (size_t)(m0 + arow) * KP + acol8 * 8;

        // prologue: stage 0
        cpasync16(smbase + a_dst_o,  Abase);
        cpasync16(smbase + wh_dst_o, Whb);
        cpasync16(smbase + wl_dst_o, Wlb);
        asm volatile("cp.async.commit_group;");

        float acc[2][4][4] = {};

        for (int it = 0; it < NITER; it++) {
            asm volatile("cp.async.wait_group 0;");
            __syncthreads();
            if (it + 1 < NITER) {
                const uint32_t sb = smbase + ((it + 1) & 1) * STAGE_B;
                const int k0 = (it + 1) * 16;
                cpasync16(sb + a_dst_o,  Abase + k0);
                cpasync16(sb + wh_dst_o, Whb + k0);
                cpasync16(sb + wl_dst_o, Wlb + k0);
                asm volatile("cp.async.commit_group;");
            }
            const uint32_t* S = (const uint32_t*)(smbuf + (it & 1) * STAGE_B);

            uint32_t ah[2][4], al[2][4], bh[4][2], bl[4][2];
            #pragma unroll
            for (int i = 0; i < 2; i++) {
                int row = warp_m * 32 + i * 16 + r;
                ah[i][0] = S[row * 12 + q];
                ah[i][1] = S[(row + 8) * 12 + q];
                ah[i][2] = S[row * 12 + q + 4];
                ah[i][3] = S[(row + 8) * 12 + q + 4];
                al[i][0] = S[768 + row * 12 + q];
                al[i][1] = S[768 + (row + 8) * 12 + q];
                al[i][2] = S[768 + row * 12 + q + 4];
                al[i][3] = S[768 + (row + 8) * 12 + q + 4];
            }
            #pragma unroll
            for (int j = 0; j < 4; j++) {
                int nrow = warp_n * 32 + j * 8 + r;
                bh[j][0] = S[1536 + nrow * 12 + q];
                bh[j][1] = S[1536 + nrow * 12 + q + 4];
                bl[j][0] = S[3072 + nrow * 12 + q];
                bl[j][1] = S[3072 + nrow * 12 + q + 4];
            }
            #pragma unroll
            for (int i = 0; i < 2; i++)
                #pragma unroll
                for (int j = 0; j < 4; j++) {
                    mma16816(acc[i][j], ah[i], bh[j]);
                    mma16816(acc[i][j], ah[i], bl[j]);
                    mma16816(acc[i][j], al[i], bh[j]);
                }
        }

        // ----------------- fused LSTM epilogue -----------------
        const size_t A1 = (size_t)(p ^ 1) * BATCH * KP;
        const int parity = q & 1;
        const int jj = q >> 1;

        #pragma unroll
        for (int i = 0; i < 2; i++) {
            float d0 = 0.f, d1 = 0.f, d2 = 0.f, d3 = 0.f;
            const int row_blk = warp_m * 32 + i * 16 + r + parity * 8;
            const int b = m0 + row_blk;
            #pragma unroll
            for (int j = 0; j < 4; j++) {
                float c0 = acc[i][j][0], c1 = acc[i][j][1], c2 = acc[i][j][2], c3 = acc[i][j][3];
                float p0 = __shfl_xor_sync(0xffffffffu, c0, 1);
                float p1 = __shfl_xor_sync(0xffffffffu, c1, 1);
                float p2 = __shfl_xor_sync(0xffffffffu, c2, 1);
                float p3 = __shfl_xor_sync(0xffffffffu, c3, 1);
                float gi, gf, gg, go;
                if (!parity) { gi = c0; gf = c1; gg = p0; go = p1; }
                else         { gi = p2; gf = p3; gg = c2; go = c3; }
                const int jg = (n0 >> 2) + warp_n * 8 + j * 2 + jj;
                float4 bv = *(const float4*)(g_bint + 4 * jg);
                gi += bv.x; gf += bv.y; gg += bv.z; go += bv.w;
                float co = g_c[b * HIDDEN + jg];
                float cn = sigf(gf) * co + sigf(gi) * tanhfast(gg);
                float h  = sigf(go) * tanhfast(cn);
                g_c[b * HIDDEN + jg] = cn;
                out[((size_t)b * SEQ + t) * ZS + 2 + jg] = h;
                __nv_bfloat16 hh, hl;
                bf16split(h, &hh, &hl);
                g_Ahi[A1 + (size_t)b * KP + 132 + jg] = hh;
                g_Alo[A1 + (size_t)b * KP + 132 + jg] = hl;
                d0 += h * alpha_w[jg];
                d1 += h * alpha_w[HIDDEN + jg];
                d2 += h * Whx_w[jg];
                d3 += h * Whx_w[HIDDEN + jg];
            }
            d0 += __shfl_xor_sync(0xffffffffu, d0, 2);
            d1 += __shfl_xor_sync(0xffffffffu, d1, 2);
            d2 += __shfl_xor_sync(0xffffffffu, d2, 2);
            d3 += __shfl_xor_sync(0xffffffffu, d3, 2);
            if (q < 2) partsm[row_blk][warp_n] = make_float4(d0, d1, d2, d3);
        }
        __syncthreads();
        if (tid < 64) {
            float4 a = partsm[tid][0], bb = partsm[tid][1],
                   c = partsm[tid][2], d = partsm[tid][3];
            float4 s = make_float4(a.x + bb.x + c.x + d.x, a.y + bb.y + c.y + d.y,
                                   a.z + bb.z + c.z + d.z, a.w + bb.w + c.w + d.w);
            g_part[((size_t)(p * 4 + grp) * 64 + tid) * 32 + nblk] = s;
        }

        // stage u_{t+1}: this CTA covers 2 of the 64 rows
        if (t + 1 < SEQ) {
            int row = 2 * nblk + (tid >> 7);
            int col = tid & 127;
            int b = m0 + row;
            float u = rnn_input[((size_t)b * SEQ + (t + 1)) * INPUT + col];
            __nv_bfloat16 hi, lo;
            bf16split(u, &hi, &lo);
            g_Ahi[A1 + (size_t)b * KP + 4 + col] = hi;
            g_Alo[A1 + (size_t)b * KP + 4 + col] = lo;
        }

        // ---- group barrier ----
        __threadfence();
        __syncthreads();
        target += 32;
        if (tid == 0) {
            atomicAdd(&g_ctr[grp], 1u);
            volatile unsigned int* vp = &g_ctr[grp];
            while (*vp < target) __nanosleep(64);
        }
        __syncthreads();
        __threadfence();

        // ---- replicated x-update: 8 warps x 8 rows ----
        {
            const float4* pp = g_part + (size_t)(p * 4 + grp) * 64 * 32;
            #pragma unroll
            for (int rr = 0; rr < 8; rr++) {
                int row = wid * 8 + rr;
                float4 v = __ldcg(pp + row * 32 + lane);
                #pragma unroll
                for (int off = 16; off > 0; off >>= 1) {
                    v.x += __shfl_xor_sync(0xffffffffu, v.x, off);
                    v.y += __shfl_xor_sync(0xffffffffu, v.y, off);
                    v.z += __shfl_xor_sync(0xffffffffu, v.z, off);
                    v.w += __shfl_xor_sync(0xffffffffu, v.w, off);
                }
                if (lane == 0) {
                    int b = m0 + row;
                    float al0 = sigf(v.x + alpha_b[0]);
                    float al1 = sigf(v.y + alpha_b[1]);
                    float hx0 = v.z + Whx_b[0];
                    float hx1 = v.w + Whx_b[1];
                    float x0 = __ldcg(&g_x[p * BATCH * 2 + b * 2]);
                    float x1 = __ldcg(&g_x[p * BATCH * 2 + b * 2 + 1]);
                    float tv = tau[(size_t)b * SEQ + t];
                    float xm0 = (1.f + tv * MHU) * x0 - (tv * MHU) * x1;
                    float xm1 = tv * (1.f / MHU) * x0 + x1;
                    float xn0 = al0 * xm0 + (1.f - al0) * hx0;
                    float xn1 = al1 * xm1 + (1.f - al1) * hx1;
                    g_x[(p ^ 1) * BATCH * 2 + b * 2]     = xn0;
                    g_x[(p ^ 1) * BATCH * 2 + b * 2 + 1] = xn1;
                    float* orow = out + ((size_t)b * SEQ + t) * ZS;
                    orow[0] = xn0; orow[1] = xn1;
                    __nv_bfloat16 hi, lo;
                    bf16split(xn0, &hi, &lo);
                    g_Ahi[A1 + (size_t)b * KP + 0] = hi;
                    g_Alo[A1 + (size_t)b * KP + 0] = lo;
                    bf16split(xn1, &hi, &lo);
                    g_Ahi[A1 + (size_t)b * KP + 1] = hi;
                    g_Alo[A1 + (size_t)b * KP + 1] = lo;
                }
            }
        }
        __syncthreads();
    }
}

// ---------------------------------------------------------------------------
__global__ void finalize(const float* __restrict__ c_z0, float* __restrict__ out) {
    int b = blockIdx.x, tid = threadIdx.x;
    size_t base = (size_t)BATCH * SEQ * ZS;
    float* zf  = out + base + (size_t)b * ZS;
    float* czf = out + base + (size_t)BATCH * ZS + (size_t)b * ZS;
    const float* last = out + ((size_t)b * SEQ + (SEQ - 1)) * ZS;
    for (int k = tid; k < ZS; k += 256) {
        zf[k]  = last[k];
        czf[k] = (k < 2) ? c_z0[b * ZS + k] : g_c[(size_t)b * HIDDEN + (k - 2)];
    }
}

// ---------------------------------------------------------------------------
extern "C" void kernel_launch(void* const* d_in, const int* in_sizes, int n_in,
                              void* d_out, int out_size) {
    const float* rnn_input = (const float*)d_in[0];
    const float* tau       = (const float*)d_in[1];
    const float* z0        = (const float*)d_in[2];
    const float* c_z0      = (const float*)d_in[3];
    const float* WU_w      = (const float*)d_in[4];
    const float* WU_b      = (const float*)d_in[5];
    const float* alpha_w   = (const float*)d_in[6];
    const float* alpha_b   = (const float*)d_in[7];
    const float* Whx_w     = (const float*)d_in[8];
    const float* Whx_b     = (const float*)d_in[9];
    float* out = (float*)d_out;

    repack<<<4096, 256>>>(WU_w, WU_b);
    init_state<<<BATCH, 256>>>(z0, c_z0, rnn_input);
    persistent_rnn<<<128, 256>>>(rnn_input, tau, alpha_w, alpha_b,
                                 Whx_w, Whx_b, out);
    finalize<<<BATCH, 256>>>(c_z0, out);
}

// round 7
// speedup vs baseline: 1.0471x; 1.0471x over previous
#include <cuda_runtime.h>
#include <cuda_fp16.h>
#include <math.h>
#include <stdint.h>

#define BATCH   256
#define SEQ     256
#define INPUT   128
#define HIDDEN  1024
#define ZS      1026
#define NG      4096          // 4*HIDDEN interleaved: col n' = 4*j + gate
#define KIN     1154
#define KP      1168          // padded K (73*16)
#define NITER   73
#define MHU     1.5f

// Activation column layout: [x(2) | pad(2) | u(128) | h(1024) | pad(12)]
// A is split fp16 hi+lo (2-product scheme); W is single fp16.
__device__ __align__(16) __half g_W  [NG * KP];
__device__ __align__(16) float  g_bint[NG];
__device__ __align__(16) __half g_Ahi[2 * BATCH * KP];
__device__ __align__(16) __half g_Alo[2 * BATCH * KP];
__device__ __align__(16) float  g_c[BATCH * HIDDEN];
__device__ __align__(16) float  g_x[2 * BATCH * 2];
__device__ __align__(16) float4 g_part[2 * 4 * 64 * 32]; // [p][grp][row][nblk]
__device__ unsigned int         g_ctr[4];

__device__ __forceinline__ float sigf(float x) {
    return __fdividef(1.f, 1.f + __expf(-x));
}
__device__ __forceinline__ float tanhfast(float x) {
    return 2.f * sigf(2.f * x) - 1.f;
}
__device__ __forceinline__ void h16split(float v, __half* hi, __half* lo) {
    __half h = __float2half(v);
    *hi = h;
    *lo = __float2half(v - __half2float(h));
}
__device__ __forceinline__ void mma16816(float* c, const uint32_t* a, const uint32_t* b) {
    asm volatile(
        "mma.sync.aligned.m16n8k16.row.col.f32.f16.f16.f32 "
        "{%0,%1,%2,%3}, {%4,%5,%6,%7}, {%8,%9}, {%0,%1,%2,%3};"
        : "+f"(c[0]), "+f"(c[1]), "+f"(c[2]), "+f"(c[3])
        : "r"(a[0]), "r"(a[1]), "r"(a[2]), "r"(a[3]), "r"(b[0]), "r"(b[1]));
}
__device__ __forceinline__ void cpasync16(uint32_t dst, const void* src) {
    asm volatile("cp.async.cg.shared.global [%0], [%1], 16;" :: "r"(dst), "l"(src));
}

// ---------------------------------------------------------------------------
// Repack weights: interleave gates, pad K, cast to fp16. Bias interleave.
// ---------------------------------------------------------------------------
__global__ void repack(const float* __restrict__ WU_w, const float* __restrict__ WU_b) {
    int idx = blockIdx.x * blockDim.x + threadIdx.x;
    const int total = NG * KP;
    for (int i = idx; i < total; i += gridDim.x * blockDim.x) {
        int np = i / KP;
        int k  = i - np * KP;
        int j  = np >> 2;
        int g  = np & 3;
        int n  = g * HIDDEN + j;
        float v = 0.f;
        if (k < 2)                   v = WU_w[(size_t)n * KIN + k];
        else if (k >= 4 && k < 1156) v = WU_w[(size_t)n * KIN + (k - 2)];
        g_W[i] = __float2half(v);
    }
    if (idx < NG) {
        int j = idx >> 2, g = idx & 3;
        g_bint[idx] = WU_b[g * HIDDEN + j];
    }
}

// ---------------------------------------------------------------------------
// Init activation matrix (x, u_0, h), cell state, x state, counters.
// ---------------------------------------------------------------------------
__global__ void init_state(const float* __restrict__ z0,
                           const float* __restrict__ c_z0,
                           const float* __restrict__ rnn_input) {
    int b = blockIdx.x, tid = threadIdx.x;
    for (int k = tid; k < KP; k += 256) {
        float v = 0.f;
        if (k < 2)                     v = z0[b * ZS + k];
        else if (k >= 4 && k < 132)    v = rnn_input[(size_t)b * SEQ * INPUT + (k - 4)];
        else if (k >= 132 && k < 1156) v = z0[b * ZS + 2 + (k - 132)];
        __half hi, lo;
        h16split(v, &hi, &lo);
        g_Ahi[b * KP + k] = hi;
        g_Alo[b * KP + k] = lo;
    }
    if (tid < 2) g_x[b * 2 + tid] = z0[b * ZS + tid];
    for (int j = tid; j < HIDDEN; j += 256)
        g_c[b * HIDDEN + j] = c_z0[b * ZS + 2 + j];
    if (b == 0 && tid < 4) g_ctr[tid] = 0u;
}

// ---------------------------------------------------------------------------
// Persistent kernel: 128 CTAs = 4 m-groups (64 batch rows) x 32 n-blocks
// (128 interleaved gate cols = 32 hidden units each). Per step: 2-product
// fp16 mma GEMM + fused LSTM epilogue + group spin-barrier + x-update.
// smem stage layout (bytes): Ahi[0,3072) Alo[3072,6144) W[6144,12288)
// ---------------------------------------------------------------------------
#define STAGE_B 12288

__global__ void __launch_bounds__(256) persistent_rnn(
    const float* __restrict__ rnn_input, const float* __restrict__ tau,
    const float* __restrict__ alpha_w,   const float* __restrict__ alpha_b,
    const float* __restrict__ Whx_w,     const float* __restrict__ Whx_b,
    float* __restrict__ out)
{
    __shared__ __align__(16) unsigned char smbuf[2 * STAGE_B];
    __shared__ __align__(16) float4 partsm[64][4];

    const int tid  = threadIdx.x;
    const int grp  = blockIdx.x >> 5;
    const int nblk = blockIdx.x & 31;
    const int m0   = grp * 64;
    const int n0   = nblk * 128;
    const int lane = tid & 31, wid = tid >> 5;
    const int warp_m = wid >> 2, warp_n = wid & 3;
    const int r = lane >> 2, q = lane & 3;

    // staging assignments:
    //  A: threads 0-127 -> hi slab, 128-255 -> lo slab; 64 rows x 2 16B chunks
    //  W: all 256 threads -> 128 rows x 2 16B chunks
    const int arow = (tid & 127) >> 1, acol8 = tid & 1;
    const int wrow = tid >> 1,         wcol8 = tid & 1;
    const bool aIsHi = tid < 128;

    const uint32_t smbase  = (uint32_t)__cvta_generic_to_shared(smbuf);
    const uint32_t a_dst_o = (aIsHi ? 0u : 3072u) + arow * 48 + acol8 * 16;
    const uint32_t w_dst_o = 6144u + wrow * 48 + wcol8 * 16;

    const __half* Wb = g_W + (size_t)(n0 + wrow) * KP + wcol8 * 8;

    unsigned int target = 0;

    for (int t = 0; t < SEQ; t++) {
        const int p = t & 1;
        const __half* Abase =
            (aIsHi ? g_Ahi : g_Alo) + (size_t)p * BATCH * KP
            + (size_t)(m0 + arow) * KP + acol8 * 8;

        // prologue: stage 0
        cpasync16(smbase + a_dst_o, Abase);
        cpasync16(smbase + w_dst_o, Wb);
        asm volatile("cp.async.commit_group;");

        float acc[2][4][4] = {};

        for (int it = 0; it < NITER; it++) {
            asm volatile("cp.async.wait_group 0;");
            __syncthreads();
            if (it + 1 < NITER) {
                const uint32_t sb = smbase + ((it + 1) & 1) * STAGE_B;
                const int k0 = (it + 1) * 16;
                cpasync16(sb + a_dst_o, Abase + k0);
                cpasync16(sb + w_dst_o, Wb + k0);
                asm volatile("cp.async.commit_group;");
            }
            const uint32_t* S = (const uint32_t*)(smbuf + (it & 1) * STAGE_B);

            uint32_t ah[2][4], al[2][4], bh[4][2];
            #pragma unroll
            for (int i = 0; i < 2; i++) {
                int row = warp_m * 32 + i * 16 + r;
                ah[i][0] = S[row * 12 + q];
                ah[i][1] = S[(row + 8) * 12 + q];
                ah[i][2] = S[row * 12 + q + 4];
                ah[i][3] = S[(row + 8) * 12 + q + 4];
                al[i][0] = S[768 + row * 12 + q];
                al[i][1] = S[768 + (row + 8) * 12 + q];
                al[i][2] = S[768 + row * 12 + q + 4];
                al[i][3] = S[768 + (row + 8) * 12 + q + 4];
            }
            #pragma unroll
            for (int j = 0; j < 4; j++) {
                int nrow = warp_n * 32 + j * 8 + r;
                bh[j][0] = S[1536 + nrow * 12 + q];
                bh[j][1] = S[1536 + nrow * 12 + q + 4];
            }
            #pragma unroll
            for (int i = 0; i < 2; i++)
                #pragma unroll
                for (int j = 0; j < 4; j++) {
                    mma16816(acc[i][j], ah[i], bh[j]);
                    mma16816(acc[i][j], al[i], bh[j]);
                }
        }

        // ----------------- fused LSTM epilogue -----------------
        const size_t A1 = (size_t)(p ^ 1) * BATCH * KP;
        const int parity = q & 1;
        const int jj = q >> 1;

        #pragma unroll
        for (int i = 0; i < 2; i++) {
            float d0 = 0.f, d1 = 0.f, d2 = 0.f, d3 = 0.f;
            const int row_blk = warp_m * 32 + i * 16 + r + parity * 8;
            const int b = m0 + row_blk;
            #pragma unroll
            for (int j = 0; j < 4; j++) {
                float c0 = acc[i][j][0], c1 = acc[i][j][1], c2 = acc[i][j][2], c3 = acc[i][j][3];
                float p0 = __shfl_xor_sync(0xffffffffu, c0, 1);
                float p1 = __shfl_xor_sync(0xffffffffu, c1, 1);
                float p2 = __shfl_xor_sync(0xffffffffu, c2, 1);
                float p3 = __shfl_xor_sync(0xffffffffu, c3, 1);
                float gi, gf, gg, go;
                if (!parity) { gi = c0; gf = c1; gg = p0; go = p1; }
                else         { gi = p2; gf = p3; gg = c2; go = c3; }
                const int jg = (n0 >> 2) + warp_n * 8 + j * 2 + jj;
                float4 bv = *(const float4*)(g_bint + 4 * jg);
                gi += bv.x; gf += bv.y; gg += bv.z; go += bv.w;
                float co = g_c[b * HIDDEN + jg];
                float cn = sigf(gf) * co + sigf(gi) * tanhfast(gg);
                float h  = sigf(go) * tanhfast(cn);
                g_c[b * HIDDEN + jg] = cn;
                out[((size_t)b * SEQ + t) * ZS + 2 + jg] = h;
                __half hh, hl;
                h16split(h, &hh, &hl);
                g_Ahi[A1 + (size_t)b * KP + 132 + jg] = hh;
                g_Alo[A1 + (size_t)b * KP + 132 + jg] = hl;
                d0 += h * alpha_w[jg];
                d1 += h * alpha_w[HIDDEN + jg];
                d2 += h * Whx_w[jg];
                d3 += h * Whx_w[HIDDEN + jg];
            }
            d0 += __shfl_xor_sync(0xffffffffu, d0, 2);
            d1 += __shfl_xor_sync(0xffffffffu, d1, 2);
            d2 += __shfl_xor_sync(0xffffffffu, d2, 2);
            d3 += __shfl_xor_sync(0xffffffffu, d3, 2);
            if (q < 2) partsm[row_blk][warp_n] = make_float4(d0, d1, d2, d3);
        }
        __syncthreads();
        if (tid < 64) {
            float4 a = partsm[tid][0], bb = partsm[tid][1],
                   c = partsm[tid][2], d = partsm[tid][3];
            float4 s = make_float4(a.x + bb.x + c.x + d.x, a.y + bb.y + c.y + d.y,
                                   a.z + bb.z + c.z + d.z, a.w + bb.w + c.w + d.w);
            g_part[((size_t)(p * 4 + grp) * 64 + tid) * 32 + nblk] = s;
        }

        // stage u_{t+1}: this CTA covers 2 of the 64 rows
        if (t + 1 < SEQ) {
            int row = 2 * nblk + (tid >> 7);
            int col = tid & 127;
            int b = m0 + row;
            float u = rnn_input[((size_t)b * SEQ + (t + 1)) * INPUT + col];
            __half hi, lo;
            h16split(u, &hi, &lo);
            g_Ahi[A1 + (size_t)b * KP + 4 + col] = hi;
            g_Alo[A1 + (size_t)b * KP + 4 + col] = lo;
        }

        // ---- group barrier (32 CTAs) ----
        __threadfence();
        __syncthreads();
        target += 32;
        if (tid == 0) {
            atomicAdd(&g_ctr[grp], 1u);
            volatile unsigned int* vp = &g_ctr[grp];
            while (*vp < target) __nanosleep(32);
        }
        __syncthreads();
        __threadfence();

        // ---- replicated x-update: 8 warps x 8 rows ----
        {
            const float4* pp = g_part + (size_t)(p * 4 + grp) * 64 * 32;
            #pragma unroll
            for (int rr = 0; rr < 8; rr++) {
                int row = wid * 8 + rr;
                float4 v = __ldcg(pp + row * 32 + lane);
                #pragma unroll
                for (int off = 16; off > 0; off >>= 1) {
                    v.x += __shfl_xor_sync(0xffffffffu, v.x, off);
                    v.y += __shfl_xor_sync(0xffffffffu, v.y, off);
                    v.z += __shfl_xor_sync(0xffffffffu, v.z, off);
                    v.w += __shfl_xor_sync(0xffffffffu, v.w, off);
                }
                if (lane == 0) {
                    int b = m0 + row;
                    float al0 = sigf(v.x + alpha_b[0]);
                    float al1 = sigf(v.y + alpha_b[1]);
                    float hx0 = v.z + Whx_b[0];
                    float hx1 = v.w + Whx_b[1];
                    float x0 = g_x[p * BATCH * 2 + b * 2];
                    float x1 = g_x[p * BATCH * 2 + b * 2 + 1];
                    float tv = tau[(size_t)b * SEQ + t];
                    float xm0 = (1.f + tv * MHU) * x0 - (tv * MHU) * x1;
                    float xm1 = tv * (1.f / MHU) * x0 + x1;
                    float xn0 = al0 * xm0 + (1.f - al0) * hx0;
                    float xn1 = al1 * xm1 + (1.f - al1) * hx1;
                    g_x[(p ^ 1) * BATCH * 2 + b * 2]     = xn0;
                    g_x[(p ^ 1) * BATCH * 2 + b * 2 + 1] = xn1;
                    float* orow = out + ((size_t)b * SEQ + t) * ZS;
                    orow[0] = xn0; orow[1] = xn1;
                    __half hi, lo;
                    h16split(xn0, &hi, &lo);
                    g_Ahi[A1 + (size_t)b * KP + 0] = hi;
                    g_Alo[A1 + (size_t)b * KP + 0] = lo;
                    h16split(xn1, &hi, &lo);
                    g_Ahi[A1 + (size_t)b * KP + 1] = hi;
                    g_Alo[A1 + (size_t)b * KP + 1] = lo;
                }
            }
        }
        __threadfence();
        __syncthreads();
    }
}

// ---------------------------------------------------------------------------
__global__ void finalize(const float* __restrict__ c_z0, float* __restrict__ out) {
    int b = blockIdx.x, tid = threadIdx.x;
    size_t base = (size_t)BATCH * SEQ * ZS;
    float* zf  = out + base + (size_t)b * ZS;
    float* czf = out + base + (size_t)BATCH * ZS + (size_t)b * ZS;
    const float* last = out + ((size_t)b * SEQ + (SEQ - 1)) * ZS;
    for (int k = tid; k < ZS; k += 256) {
        zf[k]  = last[k];
        czf[k] = (k < 2) ? c_z0[b * ZS + k] : g_c[(size_t)b * HIDDEN + (k - 2)];
    }
}

// ---------------------------------------------------------------------------
extern "C" void kernel_launch(void* const* d_in, const int* in_sizes, int n_in,
                              void* d_out, int out_size) {
    const float* rnn_input = (const float*)d_in[0];
    const float* tau       = (const float*)d_in[1];
    const float* z0        = (const float*)d_in[2];
    const float* c_z0      = (const float*)d_in[3];
    const float* WU_w      = (const float*)d_in[4];
    const float* WU_b      = (const float*)d_in[5];
    const float* alpha_w   = (const float*)d_in[6];
    const float* alpha_b   = (const float*)d_in[7];
    const float* Whx_w     = (const float*)d_in[8];
    const float* Whx_b     = (const float*)d_in[9];
    float* out = (float*)d_out;

    repack<<<4096, 256>>>(WU_w, WU_b);
    init_state<<<BATCH, 256>>>(z0, c_z0, rnn_input);
    persistent_rnn<<<128, 256>>>(rnn_input, tau, alpha_w, alpha_b,
                                 Whx_w, Whx_b, out);
    finalize<<<BATCH, 256>>>(c_z0, out);
}

// round 8
// speedup vs baseline: 1.1984x; 1.1445x over previous
#include <cuda_runtime.h>
#include <cuda_fp16.h>
#include <math.h>
#include <stdint.h>

#define BATCH   256
#define SEQ     256
#define INPUT   128
#define HIDDEN  1024
#define ZS      1026
#define NG      4096          // 4*HIDDEN interleaved: col n' = 4*j + gate
#define KIN     1154
#define KW      1152          // GEMM K = [u(128) | h(1024)]  (x handled rank-2)
#define NIT     36            // K tiles of 32
#define MHU     1.5f

// A = [u | h] fp16, split hi/lo, double-buffered by step parity. Row stride KW.
__device__ __align__(16) __half g_W  [NG * KW];       // interleaved cols, fp16
__device__ __align__(16) float  g_Wx [NG * 2];        // W[:,0], W[:,1] (x cols), fp32
__device__ __align__(16) float  g_bint[NG];
__device__ __align__(16) __half g_Ahi[2 * BATCH * KW];
__device__ __align__(16) __half g_Alo[2 * BATCH * KW];
__device__ __align__(16) float  g_c[BATCH * HIDDEN];
__device__ __align__(16) float  g_x[2 * BATCH * 2];   // x state, parity-buffered
__device__ __align__(16) float4 g_part[2 * 4 * 64 * 32]; // [p][grp][row][nblk]

__device__ __forceinline__ float sigf(float x) {
    return __fdividef(1.f, 1.f + __expf(-x));
}
__device__ __forceinline__ float tanhfast(float x) {
    return 2.f * sigf(2.f * x) - 1.f;
}
__device__ __forceinline__ void h16split(float v, __half* hi, __half* lo) {
    __half h = __float2half(v);
    *hi = h;
    *lo = __float2half(v - __half2float(h));
}
__device__ __forceinline__ void mma16816(float* c, const uint32_t* a, const uint32_t* b) {
    asm volatile(
        "mma.sync.aligned.m16n8k16.row.col.f32.f16.f16.f32 "
        "{%0,%1,%2,%3}, {%4,%5,%6,%7}, {%8,%9}, {%0,%1,%2,%3};"
        : "+f"(c[0]), "+f"(c[1]), "+f"(c[2]), "+f"(c[3])
        : "r"(a[0]), "r"(a[1]), "r"(a[2]), "r"(a[3]), "r"(b[0]), "r"(b[1]));
}
__device__ __forceinline__ void cpasync16(uint32_t dst, const void* src) {
    asm volatile("cp.async.cg.shared.global [%0], [%1], 16;" :: "r"(dst), "l"(src));
}

// ---------------------------------------------------------------------------
// Repack: W[np][k2] fp16 (k2 = orig col k2+2), g_Wx (x cols, fp32), bias.
// ---------------------------------------------------------------------------
__global__ void repack(const float* __restrict__ WU_w, const float* __restrict__ WU_b) {
    int idx = blockIdx.x * blockDim.x + threadIdx.x;
    const int total = NG * KW;
    for (int i = idx; i < total; i += gridDim.x * blockDim.x) {
        int np = i / KW;
        int k2 = i - np * KW;
        int n  = (np & 3) * HIDDEN + (np >> 2);
        g_W[i] = __float2half(WU_w[(size_t)n * KIN + k2 + 2]);
    }
    if (idx < NG) {
        int n = (idx & 3) * HIDDEN + (idx >> 2);
        g_bint[idx] = WU_b[n];
        g_Wx[idx * 2 + 0] = WU_w[(size_t)n * KIN + 0];
        g_Wx[idx * 2 + 1] = WU_w[(size_t)n * KIN + 1];
    }
}

// ---------------------------------------------------------------------------
// Init: A[0] = [u_0 | h_z0] hi/lo, g_x[0]=g_x[1]=x_z0, g_c = c_z0.
// ---------------------------------------------------------------------------
__global__ void init_state(const float* __restrict__ z0,
                           const float* __restrict__ c_z0,
                           const float* __restrict__ rnn_input) {
    int b = blockIdx.x, tid = threadIdx.x;
    for (int k = tid; k < KW; k += 256) {
        float v = (k < 128) ? rnn_input[(size_t)b * SEQ * INPUT + k]
                            : z0[b * ZS + 2 + (k - 128)];
        __half hi, lo;
        h16split(v, &hi, &lo);
        g_Ahi[(size_t)b * KW + k] = hi;
        g_Alo[(size_t)b * KW + k] = lo;
    }
    if (tid < 2) {
        float xv = z0[b * ZS + tid];
        g_x[b * 2 + tid] = xv;
        g_x[BATCH * 2 + b * 2 + tid] = xv;
    }
    for (int j = tid; j < HIDDEN; j += 256)
        g_c[b * HIDDEN + j] = c_z0[b * ZS + 2 + j];
}

// ---------------------------------------------------------------------------
// Per-step kernel: 128 CTAs = 4 grp(64 rows) x 32 nblk(128 gate cols).
// BK=32, 3-stage cp.async ring (wait_group 1), 2-product fp16 mma.
// Epilogue: x-reduce from prev-step parts (rank-2 gate fix), LSTM pointwise.
// Dyn smem stage = Ahi(5120) | Alo(5120) | W(10240) = 20480 B, x3 stages.
// Row stride in smem: 80 B (20 words) -> conflict-free frags.
// ---------------------------------------------------------------------------
#define STG_B 20480
#define STG_W 5120            // words per stage

__global__ void __launch_bounds__(256) step_kernel(
    const float* __restrict__ rnn_input, const float* __restrict__ tau,
    const float* __restrict__ alpha_w,   const float* __restrict__ alpha_b,
    const float* __restrict__ Whx_w,     const float* __restrict__ Whx_b,
    float* __restrict__ out, int t)
{
    extern __shared__ __align__(16) uint32_t dynw[];   // 3*STG_W words
    __shared__ __align__(16) float4 partsm[64][4];
    __shared__ float2 s_wx[128];
    __shared__ float2 s_x[64];

    const int tid  = threadIdx.x;
    const int grp  = blockIdx.x >> 5;
    const int nblk = blockIdx.x & 31;
    const int m0   = grp * 64;
    const int n0   = nblk * 128;
    const int lane = tid & 31, wid = tid >> 5;
    const int warp_m = wid >> 2, warp_n = wid & 3;
    const int r = lane >> 2, q = lane & 3;
    const int p  = t & 1;
    const int pn = p ^ 1;

    if (tid < 128) {
        s_wx[tid] = make_float2(g_Wx[(n0 + tid) * 2], g_Wx[(n0 + tid) * 2 + 1]);
    }

    // staging: 4 cp.async16 per thread per stage
    const int srow = tid >> 2, sch = tid & 3;
    const __half* srcAh = g_Ahi + (size_t)p * BATCH * KW + (size_t)(m0 + srow) * KW + sch * 8;
    const __half* srcAl = g_Alo + (size_t)p * BATCH * KW + (size_t)(m0 + srow) * KW + sch * 8;
    const __half* srcW0 = g_W + (size_t)(n0 + srow) * KW + sch * 8;
    const __half* srcW1 = g_W + (size_t)(n0 + 64 + srow) * KW + sch * 8;
    const uint32_t smb = (uint32_t)__cvta_generic_to_shared(dynw);
    const uint32_t dAh = srow * 80 + sch * 16;
    const uint32_t dAl = 5120u + srow * 80 + sch * 16;
    const uint32_t dW0 = 10240u + srow * 80 + sch * 16;
    const uint32_t dW1 = 10240u + (64 + srow) * 80 + sch * 16;

    #define STG(it_) do {                                   \
        const int _it = (it_);                              \
        const uint32_t _d = smb + (uint32_t)(_it % 3) * STG_B; \
        const int _k = _it * 32;                            \
        cpasync16(_d + dAh, srcAh + _k);                    \
        cpasync16(_d + dAl, srcAl + _k);                    \
        cpasync16(_d + dW0, srcW0 + _k);                    \
        cpasync16(_d + dW1, srcW1 + _k);                    \
        asm volatile("cp.async.commit_group;" ::: "memory"); \
    } while (0)

    STG(0);
    STG(1);

    float acc[2][4][4] = {};

    #pragma unroll 1
    for (int it = 0; it < NIT; it++) {
        if (it < NIT - 1) asm volatile("cp.async.wait_group 1;" ::: "memory");
        else              asm volatile("cp.async.wait_group 0;" ::: "memory");
        __syncthreads();
        if (it + 2 < NIT) STG(it + 2);

        const uint32_t* S = dynw + (it % 3) * STG_W;

        uint32_t ah[2][2][4], al[2][2][4], bw[4][2][2];
        #pragma unroll
        for (int i = 0; i < 2; i++) {
            const int row = warp_m * 32 + i * 16 + r;
            #pragma unroll
            for (int ks = 0; ks < 2; ks++) {
                const int off = q + ks * 8;
                ah[i][ks][0] = S[row * 20 + off];
                ah[i][ks][1] = S[(row + 8) * 20 + off];
                ah[i][ks][2] = S[row * 20 + off + 4];
                ah[i][ks][3] = S[(row + 8) * 20 + off + 4];
                al[i][ks][0] = S[1280 + row * 20 + off];
                al[i][ks][1] = S[1280 + (row + 8) * 20 + off];
                al[i][ks][2] = S[1280 + row * 20 + off + 4];
                al[i][ks][3] = S[1280 + (row + 8) * 20 + off + 4];
            }
        }
        #pragma unroll
        for (int j = 0; j < 4; j++) {
            const int nrow = warp_n * 32 + j * 8 + r;
            #pragma unroll
            for (int ks = 0; ks < 2; ks++) {
                bw[j][ks][0] = S[2560 + nrow * 20 + q + ks * 8];
                bw[j][ks][1] = S[2560 + nrow * 20 + q + ks * 8 + 4];
            }
        }
        #pragma unroll
        for (int i = 0; i < 2; i++)
            #pragma unroll
            for (int j = 0; j < 4; j++)
                #pragma unroll
                for (int ks = 0; ks < 2; ks++) {
                    mma16816(acc[i][j], ah[i][ks], bw[j][ks]);
                    mma16816(acc[i][j], al[i][ks], bw[j][ks]);
                }
    }

    // ---------------- phase A: x_t from prev-step parts ----------------
    // warp w handles rows w*8 .. w*8+7
    {
        const float4* pp = g_part + (size_t)(pn * 4 + grp) * 64 * 32;
        #pragma unroll 1
        for (int rr = 0; rr < 8; rr++) {
            const int row = wid * 8 + rr;
            const int b = m0 + row;
            float x0, x1;
            if (t == 0) {
                if (lane == 0) {
                    x0 = g_x[BATCH * 2 + b * 2];
                    x1 = g_x[BATCH * 2 + b * 2 + 1];
                }
            } else {
                float4 v = __ldcg(pp + row * 32 + lane);
                #pragma unroll
                for (int off = 16; off > 0; off >>= 1) {
                    v.x += __shfl_xor_sync(0xffffffffu, v.x, off);
                    v.y += __shfl_xor_sync(0xffffffffu, v.y, off);
                    v.z += __shfl_xor_sync(0xffffffffu, v.z, off);
                    v.w += __shfl_xor_sync(0xffffffffu, v.w, off);
                }
                if (lane == 0) {
                    float al0 = sigf(v.x + alpha_b[0]);
                    float al1 = sigf(v.y + alpha_b[1]);
                    float hx0 = v.z + Whx_b[0];
                    float hx1 = v.w + Whx_b[1];
                    float xp0 = g_x[pn * BATCH * 2 + b * 2];
                    float xp1 = g_x[pn * BATCH * 2 + b * 2 + 1];
                    float tv = tau[(size_t)b * SEQ + (t - 1)];
                    float xm0 = (1.f + tv * MHU) * xp0 - (tv * MHU) * xp1;
                    float xm1 = tv * (1.f / MHU) * xp0 + xp1;
                    x0 = al0 * xm0 + (1.f - al0) * hx0;
                    x1 = al1 * xm1 + (1.f - al1) * hx1;
                }
            }
            if (lane == 0) {
                s_x[row] = make_float2(x0, x1);
                if (nblk == 0) {
                    g_x[p * BATCH * 2 + b * 2]     = x0;
                    g_x[p * BATCH * 2 + b * 2 + 1] = x1;
                    if (t > 0) {
                        float* prow = out + ((size_t)b * SEQ + (t - 1)) * ZS;
                        prow[0] = x0;
                        prow[1] = x1;
                    }
                }
            }
        }
    }
    __syncthreads();

    // ---------------- phase B: LSTM gates + dots ----------------
    const size_t A1 = (size_t)pn * BATCH * KW;
    const int parity = q & 1;
    const int jj = q >> 1;

    #pragma unroll
    for (int i = 0; i < 2; i++) {
        float d0 = 0.f, d1 = 0.f, d2 = 0.f, d3 = 0.f;
        const int row_blk = warp_m * 32 + i * 16 + r + parity * 8;
        const int b = m0 + row_blk;
        const float2 xv = s_x[row_blk];
        #pragma unroll
        for (int j = 0; j < 4; j++) {
            float c0 = acc[i][j][0], c1 = acc[i][j][1], c2 = acc[i][j][2], c3 = acc[i][j][3];
            float p0 = __shfl_xor_sync(0xffffffffu, c0, 1);
            float p1 = __shfl_xor_sync(0xffffffffu, c1, 1);
            float p2 = __shfl_xor_sync(0xffffffffu, c2, 1);
            float p3 = __shfl_xor_sync(0xffffffffu, c3, 1);
            float gi, gf, gg, go;
            if (!parity) { gi = c0; gf = c1; gg = p0; go = p1; }
            else         { gi = p2; gf = p3; gg = c2; go = c3; }
            const int jgl = warp_n * 8 + j * 2 + jj;       // local hidden idx
            const int jg  = (n0 >> 2) + jgl;               // global hidden idx
            const int npl = 4 * jgl;
            float4 bv = *(const float4*)(g_bint + 4 * jg);
            gi += bv.x + xv.x * s_wx[npl + 0].x + xv.y * s_wx[npl + 0].y;
            gf += bv.y + xv.x * s_wx[npl + 1].x + xv.y * s_wx[npl + 1].y;
            gg += bv.z + xv.x * s_wx[npl + 2].x + xv.y * s_wx[npl + 2].y;
            go += bv.w + xv.x * s_wx[npl + 3].x + xv.y * s_wx[npl + 3].y;
            float co = g_c[b * HIDDEN + jg];
            float cn = sigf(gf) * co + sigf(gi) * tanhfast(gg);
            float h  = sigf(go) * tanhfast(cn);
            g_c[b * HIDDEN + jg] = cn;
            out[((size_t)b * SEQ + t) * ZS + 2 + jg] = h;
            __half hh, hl;
            h16split(h, &hh, &hl);
            g_Ahi[A1 + (size_t)b * KW + 128 + jg] = hh;
            g_Alo[A1 + (size_t)b * KW + 128 + jg] = hl;
            d0 += h * alpha_w[jg];
            d1 += h * alpha_w[HIDDEN + jg];
            d2 += h * Whx_w[jg];
            d3 += h * Whx_w[HIDDEN + jg];
        }
        d0 += __shfl_xor_sync(0xffffffffu, d0, 2);
        d1 += __shfl_xor_sync(0xffffffffu, d1, 2);
        d2 += __shfl_xor_sync(0xffffffffu, d2, 2);
        d3 += __shfl_xor_sync(0xffffffffu, d3, 2);
        if (q < 2) partsm[row_blk][warp_n] = make_float4(d0, d1, d2, d3);
    }
    __syncthreads();
    if (tid < 64) {
        float4 a = partsm[tid][0], bb = partsm[tid][1],
               c = partsm[tid][2], d = partsm[tid][3];
        float4 s = make_float4(a.x + bb.x + c.x + d.x, a.y + bb.y + c.y + d.y,
                               a.z + bb.z + c.z + d.z, a.w + bb.w + c.w + d.w);
        g_part[((size_t)(p * 4 + grp) * 64 + tid) * 32 + nblk] = s;
    }

    // stage u_{t+1}: this CTA covers 2 of the 64 rows
    if (t + 1 < SEQ) {
        int row = 2 * nblk + (tid >> 7);
        int col = tid & 127;
        int b = m0 + row;
        float u = rnn_input[((size_t)b * SEQ + (t + 1)) * INPUT + col];
        __half hi, lo;
        h16split(u, &hi, &lo);
        g_Ahi[A1 + (size_t)b * KW + col] = hi;
        g_Alo[A1 + (size_t)b * KW + col] = lo;
    }
}

// ---------------------------------------------------------------------------
// Finalize: x_256 from parts(255), out[:,255,0:2], z_f, cz_f.
// ---------------------------------------------------------------------------
__global__ void finalize(const float* __restrict__ tau,
                         const float* __restrict__ alpha_b, const float* __restrict__ Whx_b,
                         const float* __restrict__ c_z0, float* __restrict__ out) {
    int b = blockIdx.x, tid = threadIdx.x;
    __shared__ float2 s_xf;
    if (tid < 32) {
        const float4* pp = g_part + (size_t)(1 * 4 + (b >> 6)) * 64 * 32 + (size_t)(b & 63) * 32;
        float4 v = __ldcg(pp + tid);
        #pragma unroll
        for (int off = 16; off > 0; off >>= 1) {
            v.x += __shfl_xor_sync(0xffffffffu, v.x, off);
            v.y += __shfl_xor_sync(0xffffffffu, v.y, off);
            v.z += __shfl_xor_sync(0xffffffffu, v.z, off);
            v.w += __shfl_xor_sync(0xffffffffu, v.w, off);
        }
        if (tid == 0) {
            float al0 = sigf(v.x + alpha_b[0]);
            float al1 = sigf(v.y + alpha_b[1]);
            float hx0 = v.z + Whx_b[0];
            float hx1 = v.w + Whx_b[1];
            float xp0 = g_x[BATCH * 2 + b * 2];       // parity 1 = step 255
            float xp1 = g_x[BATCH * 2 + b * 2 + 1];
            float tv = tau[(size_t)b * SEQ + (SEQ - 1)];
            float xm0 = (1.f + tv * MHU) * xp0 - (tv * MHU) * xp1;
            float xm1 = tv * (1.f / MHU) * xp0 + xp1;
            float x0 = al0 * xm0 + (1.f - al0) * hx0;
            float x1 = al1 * xm1 + (1.f - al1) * hx1;
            float* prow = out + ((size_t)b * SEQ + (SEQ - 1)) * ZS;
            prow[0] = x0; prow[1] = x1;
            s_xf = make_float2(x0, x1);
        }
    }
    __syncthreads();
    size_t base = (size_t)BATCH * SEQ * ZS;
    float* zf  = out + base + (size_t)b * ZS;
    float* czf = out + base + (size_t)BATCH * ZS + (size_t)b * ZS;
    const float* last = out + ((size_t)b * SEQ + (SEQ - 1)) * ZS;
    for (int k = tid; k < ZS; k += 256) {
        zf[k]  = (k == 0) ? s_xf.x : (k == 1) ? s_xf.y : last[k];
        czf[k] = (k < 2) ? c_z0[b * ZS + k] : g_c[(size_t)b * HIDDEN + (k - 2)];
    }
}

// ---------------------------------------------------------------------------
extern "C" void kernel_launch(void* const* d_in, const int* in_sizes, int n_in,
                              void* d_out, int out_size) {
    const float* rnn_input = (const float*)d_in[0];
    const float* tau       = (const float*)d_in[1];
    const float* z0        = (const float*)d_in[2];
    const float* c_z0      = (const float*)d_in[3];
    const float* WU_w      = (const float*)d_in[4];
    const float* WU_b      = (const float*)d_in[5];
    const float* alpha_w   = (const float*)d_in[6];
    const float* alpha_b   = (const float*)d_in[7];
    const float* Whx_w     = (const float*)d_in[8];
    const float* Whx_b     = (const float*)d_in[9];
    float* out = (float*)d_out;

    static bool attr_set = false;
    if (!attr_set) {
        cudaFuncSetAttribute(step_kernel, cudaFuncAttributeMaxDynamicSharedMemorySize,
                             3 * STG_B);
        attr_set = true;
    }

    repack<<<4096, 256>>>(WU_w, WU_b);
    init_state<<<BATCH, 256>>>(z0, c_z0, rnn_input);
    for (int t = 0; t < SEQ; t++) {
        step_kernel<<<128, 256, 3 * STG_B>>>(rnn_input, tau, alpha_w, alpha_b,
                                             Whx_w, Whx_b, out, t);
    }
    finalize<<<BATCH, 256>>>(tau, alpha_b, Whx_b, c_z0, out);
}

// round 9
// speedup vs baseline: 1.3929x; 1.1623x over previous
#include <cuda_runtime.h>
#include <cuda_fp16.h>
#include <math.h>
#include <stdint.h>

#define BATCH   256
#define SEQ     256
#define INPUT   128
#define HIDDEN  1024
#define ZS      1026
#define NG      4096          // 4*HIDDEN interleaved: col n' = 4*j + gate
#define KIN     1154
#define KW      1152          // GEMM K = [u(128) | h(1024)]  (x handled rank-2)
#define BK      64
#define NIT     18            // K tiles of 64
#define MHU     1.5f

// smem stage layout (bytes), row stride 144 (bank-conflict-free LDSM):
//   Ahi [0, 64*144)        = [0, 9216)
//   Alo [9216, 18432)
//   W   [18432, 18432+128*144) = [18432, 36864)
#define ROWB    144
#define OFF_ALO 9216
#define OFF_W   18432
#define STG_B   36864

__device__ __align__(16) __half g_W  [NG * KW];       // interleaved cols, fp16
__device__ __align__(16) float  g_Wx [NG * 2];        // W[:,0], W[:,1] (x cols), fp32
__device__ __align__(16) float  g_bint[NG];
__device__ __align__(16) __half g_Ahi[2 * BATCH * KW];
__device__ __align__(16) __half g_Alo[2 * BATCH * KW];
__device__ __align__(16) float  g_c[BATCH * HIDDEN];
__device__ __align__(16) float  g_x[2 * BATCH * 2];   // x state, parity-buffered
__device__ __align__(16) float4 g_part[2 * 4 * 64 * 32]; // [p][grp][row][nblk]

__device__ __forceinline__ float sigf(float x) {
    return __fdividef(1.f, 1.f + __expf(-x));
}
__device__ __forceinline__ float tanhfast(float x) {
    return 2.f * sigf(2.f * x) - 1.f;
}
__device__ __forceinline__ void h16split(float v, __half* hi, __half* lo) {
    __half h = __float2half(v);
    *hi = h;
    *lo = __float2half(v - __half2float(h));
}
__device__ __forceinline__ void mma16816(float* c, const uint32_t* a, const uint32_t* b) {
    asm volatile(
        "mma.sync.aligned.m16n8k16.row.col.f32.f16.f16.f32 "
        "{%0,%1,%2,%3}, {%4,%5,%6,%7}, {%8,%9}, {%0,%1,%2,%3};"
        : "+f"(c[0]), "+f"(c[1]), "+f"(c[2]), "+f"(c[3])
        : "r"(a[0]), "r"(a[1]), "r"(a[2]), "r"(a[3]), "r"(b[0]), "r"(b[1]));
}
__device__ __forceinline__ void ldsm4(uint32_t* r, uint32_t addr) {
    asm volatile(
        "ldmatrix.sync.aligned.m8n8.x4.shared.b16 {%0,%1,%2,%3}, [%4];"
        : "=r"(r[0]), "=r"(r[1]), "=r"(r[2]), "=r"(r[3]) : "r"(addr));
}
__device__ __forceinline__ void cpasync16(uint32_t dst, const void* src) {
    asm volatile("cp.async.cg.shared.global [%0], [%1], 16;" :: "r"(dst), "l"(src));
}

// ---------------------------------------------------------------------------
__global__ void repack(const float* __restrict__ WU_w, const float* __restrict__ WU_b) {
    int idx = blockIdx.x * blockDim.x + threadIdx.x;
    const int total = NG * KW;
    for (int i = idx; i < total; i += gridDim.x * blockDim.x) {
        int np = i / KW;
        int k2 = i - np * KW;
        int n  = (np & 3) * HIDDEN + (np >> 2);
        g_W[i] = __float2half(WU_w[(size_t)n * KIN + k2 + 2]);
    }
    if (idx < NG) {
        int n = (idx & 3) * HIDDEN + (idx >> 2);
        g_bint[idx] = WU_b[n];
        g_Wx[idx * 2 + 0] = WU_w[(size_t)n * KIN + 0];
        g_Wx[idx * 2 + 1] = WU_w[(size_t)n * KIN + 1];
    }
}

__global__ void init_state(const float* __restrict__ z0,
                           const float* __restrict__ c_z0,
                           const float* __restrict__ rnn_input) {
    int b = blockIdx.x, tid = threadIdx.x;
    for (int k = tid; k < KW; k += 256) {
        float v = (k < 128) ? rnn_input[(size_t)b * SEQ * INPUT + k]
                            : z0[b * ZS + 2 + (k - 128)];
        __half hi, lo;
        h16split(v, &hi, &lo);
        g_Ahi[(size_t)b * KW + k] = hi;
        g_Alo[(size_t)b * KW + k] = lo;
    }
    if (tid < 2) {
        float xv = z0[b * ZS + tid];
        g_x[b * 2 + tid] = xv;
        g_x[BATCH * 2 + b * 2 + tid] = xv;
    }
    for (int j = tid; j < HIDDEN; j += 256)
        g_c[b * HIDDEN + j] = c_z0[b * ZS + 2 + j];
}

// ---------------------------------------------------------------------------
// Per-step kernel: 128 CTAs = 4 grp(64 rows) x 32 nblk(128 gate cols).
// BK=64 (18 iters), 3-stage cp.async ring, ldmatrix fragments, 2-product
// fp16 mma. Epilogue: x from prev-step parts (rank-2 fix) + LSTM pointwise.
// ---------------------------------------------------------------------------
__global__ void __launch_bounds__(256) step_kernel(
    const float* __restrict__ rnn_input, const float* __restrict__ tau,
    const float* __restrict__ alpha_w,   const float* __restrict__ alpha_b,
    const float* __restrict__ Whx_w,     const float* __restrict__ Whx_b,
    float* __restrict__ out, int t)
{
    extern __shared__ __align__(16) unsigned char dynsm[];   // 3*STG_B
    __shared__ __align__(16) float4 partsm[64][4];
    __shared__ float2 s_wx[128];
    __shared__ float2 s_x[64];

    const int tid  = threadIdx.x;
    const int grp  = blockIdx.x >> 5;
    const int nblk = blockIdx.x & 31;
    const int m0   = grp * 64;
    const int n0   = nblk * 128;
    const int lane = tid & 31, wid = tid >> 5;
    const int warp_m = wid >> 2, warp_n = wid & 3;
    const int r = lane >> 2, q = lane & 3;
    const int p  = t & 1;
    const int pn = p ^ 1;

    if (tid < 128)
        s_wx[tid] = make_float2(g_Wx[(n0 + tid) * 2], g_Wx[(n0 + tid) * 2 + 1]);

    // ---- staging: 8 cp.async16 per thread per stage ----
    // A slots (hi then lo): 64 rows x 8 chunks = 512 per matrix -> 2 each
    // W slots: 128 rows x 8 chunks = 1024 -> 4 each
    const uint32_t smb = (uint32_t)__cvta_generic_to_shared(dynsm);
    const int arow0 = tid >> 3, ach = tid & 7;            // slot tid
    const int arow1 = (tid + 256) >> 3;                   // slot tid+256
    const __half* srcAh = g_Ahi + (size_t)p * BATCH * KW + (size_t)m0 * KW;
    const __half* srcAl = g_Alo + (size_t)p * BATCH * KW + (size_t)m0 * KW;
    const __half* srcW  = g_W + (size_t)n0 * KW;

    #define STG(it_) do {                                                        \
        const int _it = (it_);                                                   \
        const uint32_t _d = smb + (uint32_t)(_it % 3) * STG_B;                   \
        const int _kb = _it * 128;  /* bytes along K */                          \
        cpasync16(_d + arow0 * ROWB + ach * 16,                                  \
                  (const char*)(srcAh + (size_t)arow0 * KW) + _kb + ach * 16);   \
        cpasync16(_d + arow1 * ROWB + ach * 16,                                  \
                  (const char*)(srcAh + (size_t)arow1 * KW) + _kb + ach * 16);   \
        cpasync16(_d + OFF_ALO + arow0 * ROWB + ach * 16,                        \
                  (const char*)(srcAl + (size_t)arow0 * KW) + _kb + ach * 16);   \
        cpasync16(_d + OFF_ALO + arow1 * ROWB + ach * 16,                        \
                  (const char*)(srcAl + (size_t)arow1 * KW) + _kb + ach * 16);   \
        _Pragma("unroll")                                                        \
        for (int _j = 0; _j < 4; _j++) {                                         \
            const int _row = (tid + _j * 256) >> 3;                              \
            cpasync16(_d + OFF_W + _row * ROWB + ach * 16,                       \
                      (const char*)(srcW + (size_t)_row * KW) + _kb + ach * 16); \
        }                                                                        \
        asm volatile("cp.async.commit_group;" ::: "memory");                     \
    } while (0)

    STG(0);
    STG(1);

    // ---- per-lane ldmatrix row offsets (bytes within stage) ----
    // A x4: lanes 0-7 rows m+0..7 @k0 | 8-15 rows m+8..15 @k0
    //       16-23 rows m+0..7 @k8 | 24-31 rows m+8..15 @k8
    const int aRow = warp_m * 32 + (lane & 7) + ((lane >> 3) & 1) * 8;
    const uint32_t aOff = (uint32_t)(aRow * ROWB + (lane >> 4) * 16);
    // B x4: r0,r1 = frag j(2p): n rows +0..7 @k0,k8 ; r2,r3 = j(2p+1): rows +8..15
    const int bRow = warp_n * 32 + (lane & 7) + ((lane >> 4) & 1) * 8;
    const uint32_t bOff = (uint32_t)(OFF_W + bRow * ROWB + ((lane >> 3) & 1) * 16);

    float acc[2][4][4] = {};

    #pragma unroll 1
    for (int it = 0; it < NIT; it++) {
        if (it < NIT - 1) asm volatile("cp.async.wait_group 1;" ::: "memory");
        else              asm volatile("cp.async.wait_group 0;" ::: "memory");
        __syncthreads();
        if (it + 2 < NIT) STG(it + 2);

        const uint32_t S = smb + (uint32_t)(it % 3) * STG_B;
        const uint32_t aBase = S + aOff;
        const uint32_t bBase = S + bOff;

        #pragma unroll
        for (int c = 0; c < 4; c++) {
            const uint32_t kb = c * 32;   // 16 halves per chunk
            uint32_t ah[2][4], al[2][4], bw[2][4];
            ldsm4(ah[0], aBase + kb);
            ldsm4(ah[1], aBase + 16 * ROWB + kb);
            ldsm4(al[0], aBase + OFF_ALO + kb);
            ldsm4(al[1], aBase + OFF_ALO + 16 * ROWB + kb);
            ldsm4(bw[0], bBase + kb);
            ldsm4(bw[1], bBase + 16 * ROWB + kb);
            #pragma unroll
            for (int i = 0; i < 2; i++)
                #pragma unroll
                for (int jp = 0; jp < 2; jp++) {
                    mma16816(acc[i][jp * 2 + 0], ah[i], bw[jp] + 0);
                    mma16816(acc[i][jp * 2 + 0], al[i], bw[jp] + 0);
                    mma16816(acc[i][jp * 2 + 1], ah[i], bw[jp] + 2);
                    mma16816(acc[i][jp * 2 + 1], al[i], bw[jp] + 2);
                }
        }
    }

    // ---------------- phase A: x_t from prev-step parts ----------------
    {
        const float4* pp = g_part + (size_t)(pn * 4 + grp) * 64 * 32;
        #pragma unroll 1
        for (int rr = 0; rr < 8; rr++) {
            const int row = wid * 8 + rr;
            const int b = m0 + row;
            float x0, x1;
            if (t == 0) {
                if (lane == 0) {
                    x0 = g_x[BATCH * 2 + b * 2];
                    x1 = g_x[BATCH * 2 + b * 2 + 1];
                }
            } else {
                float4 v = __ldcg(pp + row * 32 + lane);
                #pragma unroll
                for (int off = 16; off > 0; off >>= 1) {
                    v.x += __shfl_xor_sync(0xffffffffu, v.x, off);
                    v.y += __shfl_xor_sync(0xffffffffu, v.y, off);
                    v.z += __shfl_xor_sync(0xffffffffu, v.z, off);
                    v.w += __shfl_xor_sync(0xffffffffu, v.w, off);
                }
                if (lane == 0) {
                    float al0 = sigf(v.x + alpha_b[0]);
                    float al1 = sigf(v.y + alpha_b[1]);
                    float hx0 = v.z + Whx_b[0];
                    float hx1 = v.w + Whx_b[1];
                    float xp0 = g_x[pn * BATCH * 2 + b * 2];
                    float xp1 = g_x[pn * BATCH * 2 + b * 2 + 1];
                    float tv = tau[(size_t)b * SEQ + (t - 1)];
                    float xm0 = (1.f + tv * MHU) * xp0 - (tv * MHU) * xp1;
                    float xm1 = tv * (1.f / MHU) * xp0 + xp1;
                    x0 = al0 * xm0 + (1.f - al0) * hx0;
                    x1 = al1 * xm1 + (1.f - al1) * hx1;
                }
            }
            if (lane == 0) {
                s_x[row] = make_float2(x0, x1);
                if (nblk == 0) {
                    g_x[p * BATCH * 2 + b * 2]     = x0;
                    g_x[p * BATCH * 2 + b * 2 + 1] = x1;
                    if (t > 0) {
                        float* prow = out + ((size_t)b * SEQ + (t - 1)) * ZS;
                        prow[0] = x0;
                        prow[1] = x1;
                    }
                }
            }
        }
    }
    __syncthreads();

    // ---------------- phase B: LSTM gates + dots ----------------
    const size_t A1 = (size_t)pn * BATCH * KW;
    const int parity = q & 1;
    const int jj = q >> 1;

    #pragma unroll
    for (int i = 0; i < 2; i++) {
        float d0 = 0.f, d1 = 0.f, d2 = 0.f, d3 = 0.f;
        const int row_blk = warp_m * 32 + i * 16 + r + parity * 8;
        const int b = m0 + row_blk;
        const float2 xv = s_x[row_blk];
        #pragma unroll
        for (int j = 0; j < 4; j++) {
            float c0 = acc[i][j][0], c1 = acc[i][j][1], c2 = acc[i][j][2], c3 = acc[i][j][3];
            float p0 = __shfl_xor_sync(0xffffffffu, c0, 1);
            float p1 = __shfl_xor_sync(0xffffffffu, c1, 1);
            float p2 = __shfl_xor_sync(0xffffffffu, c2, 1);
            float p3 = __shfl_xor_sync(0xffffffffu, c3, 1);
            float gi, gf, gg, go;
            if (!parity) { gi = c0; gf = c1; gg = p0; go = p1; }
            else         { gi = p2; gf = p3; gg = c2; go = c3; }
            const int jgl = warp_n * 8 + j * 2 + jj;       // local hidden idx
            const int jg  = (n0 >> 2) + jgl;               // global hidden idx
            const int npl = 4 * jgl;
            float4 bv = *(const float4*)(g_bint + 4 * jg);
            gi += bv.x + xv.x * s_wx[npl + 0].x + xv.y * s_wx[npl + 0].y;
            gf += bv.y + xv.x * s_wx[npl + 1].x + xv.y * s_wx[npl + 1].y;
            gg += bv.z + xv.x * s_wx[npl + 2].x + xv.y * s_wx[npl + 2].y;
            go += bv.w + xv.x * s_wx[npl + 3].x + xv.y * s_wx[npl + 3].y;
            float co = g_c[b * HIDDEN + jg];
            float cn = sigf(gf) * co + sigf(gi) * tanhfast(gg);
            float h  = sigf(go) * tanhfast(cn);
            g_c[b * HIDDEN + jg] = cn;
            out[((size_t)b * SEQ + t) * ZS + 2 + jg] = h;
            __half hh, hl;
            h16split(h, &hh, &hl);
            g_Ahi[A1 + (size_t)b * KW + 128 + jg] = hh;
            g_Alo[A1 + (size_t)b * KW + 128 + jg] = hl;
            d0 += h * alpha_w[jg];
            d1 += h * alpha_w[HIDDEN + jg];
            d2 += h * Whx_w[jg];
            d3 += h * Whx_w[HIDDEN + jg];
        }
        d0 += __shfl_xor_sync(0xffffffffu, d0, 2);
        d1 += __shfl_xor_sync(0xffffffffu, d1, 2);
        d2 += __shfl_xor_sync(0xffffffffu, d2, 2);
        d3 += __shfl_xor_sync(0xffffffffu, d3, 2);
        if (q < 2) partsm[row_blk][warp_n] = make_float4(d0, d1, d2, d3);
    }
    __syncthreads();
    if (tid < 64) {
        float4 a = partsm[tid][0], bb = partsm[tid][1],
               c = partsm[tid][2], d = partsm[tid][3];
        float4 s = make_float4(a.x + bb.x + c.x + d.x, a.y + bb.y + c.y + d.y,
                               a.z + bb.z + c.z + d.z, a.w + bb.w + c.w + d.w);
        g_part[((size_t)(p * 4 + grp) * 64 + tid) * 32 + nblk] = s;
    }

    // stage u_{t+1}: this CTA covers 2 of the 64 rows
    if (t + 1 < SEQ) {
        int row = 2 * nblk + (tid >> 7);
        int col = tid & 127;
        int b = m0 + row;
        float u = rnn_input[((size_t)b * SEQ + (t + 1)) * INPUT + col];
        __half hi, lo;
        h16split(u, &hi, &lo);
        g_Ahi[A1 + (size_t)b * KW + col] = hi;
        g_Alo[A1 + (size_t)b * KW + col] = lo;
    }
}

// ---------------------------------------------------------------------------
__global__ void finalize(const float* __restrict__ tau,
                         const float* __restrict__ alpha_b, const float* __restrict__ Whx_b,
                         const float* __restrict__ c_z0, float* __restrict__ out) {
    int b = blockIdx.x, tid = threadIdx.x;
    __shared__ float2 s_xf;
    if (tid < 32) {
        const float4* pp = g_part + (size_t)(1 * 4 + (b >> 6)) * 64 * 32 + (size_t)(b & 63) * 32;
        float4 v = __ldcg(pp + tid);
        #pragma unroll
        for (int off = 16; off > 0; off >>= 1) {
            v.x += __shfl_xor_sync(0xffffffffu, v.x, off);
            v.y += __shfl_xor_sync(0xffffffffu, v.y, off);
            v.z += __shfl_xor_sync(0xffffffffu, v.z, off);
            v.w += __shfl_xor_sync(0xffffffffu, v.w, off);
        }
        if (tid == 0) {
            float al0 = sigf(v.x + alpha_b[0]);
            float al1 = sigf(v.y + alpha_b[1]);
            float hx0 = v.z + Whx_b[0];
            float hx1 = v.w + Whx_b[1];
            float xp0 = g_x[BATCH * 2 + b * 2];       // parity 1 = step 255
            float xp1 = g_x[BATCH * 2 + b * 2 + 1];
            float tv = tau[(size_t)b * SEQ + (SEQ - 1)];
            float xm0 = (1.f + tv * MHU) * xp0 - (tv * MHU) * xp1;
            float xm1 = tv * (1.f / MHU) * xp0 + xp1;
            float x0 = al0 * xm0 + (1.f - al0) * hx0;
            float x1 = al1 * xm1 + (1.f - al1) * hx1;
            float* prow = out + ((size_t)b * SEQ + (SEQ - 1)) * ZS;
            prow[0] = x0; prow[1] = x1;
            s_xf = make_float2(x0, x1);
        }
    }
    __syncthreads();
    size_t base = (size_t)BATCH * SEQ * ZS;
    float* zf  = out + base + (size_t)b * ZS;
    float* czf = out + base + (size_t)BATCH * ZS + (size_t)b * ZS;
    const float* last = out + ((size_t)b * SEQ + (SEQ - 1)) * ZS;
    for (int k = tid; k < ZS; k += 256) {
        zf[k]  = (k == 0) ? s_xf.x : (k == 1) ? s_xf.y : last[k];
        czf[k] = (k < 2) ? c_z0[b * ZS + k] : g_c[(size_t)b * HIDDEN + (k - 2)];
    }
}

// ---------------------------------------------------------------------------
extern "C" void kernel_launch(void* const* d_in, const int* in_sizes, int n_in,
                              void* d_out, int out_size) {
    const float* rnn_input = (const float*)d_in[0];
    const float* tau       = (const float*)d_in[1];
    const float* z0        = (const float*)d_in[2];
    const float* c_z0      = (const float*)d_in[3];
    const float* WU_w      = (const float*)d_in[4];
    const float* WU_b      = (const float*)d_in[5];
    const float* alpha_w   = (const float*)d_in[6];
    const float* alpha_b   = (const float*)d_in[7];
    const float* Whx_w     = (const float*)d_in[8];
    const float* Whx_b     = (const float*)d_in[9];
    float* out = (float*)d_out;

    static bool attr_set = false;
    if (!attr_set) {
        cudaFuncSetAttribute(step_kernel, cudaFuncAttributeMaxDynamicSharedMemorySize,
                             3 * STG_B);
        attr_set = true;
    }

    repack<<<4096, 256>>>(WU_w, WU_b);
    init_state<<<BATCH, 256>>>(z0, c_z0, rnn_input);
    for (int t = 0; t < SEQ; t++) {
        step_kernel<<<128, 256, 3 * STG_B>>>(rnn_input, tau, alpha_w, alpha_b,
                                             Whx_w, Whx_b, out, t);
    }
    finalize<<<BATCH, 256>>>(tau, alpha_b, Whx_b, c_z0, out);
}

// round 10
// speedup vs baseline: 1.8888x; 1.3561x over previous
#include <cuda_runtime.h>
#include <cuda_fp16.h>
#include <math.h>
#include <stdint.h>

#define BATCH   256
#define SEQ     256
#define INPUT   128
#define HIDDEN  1024
#define ZS      1026
#define NG      4096          // 4*HIDDEN interleaved: col n' = 4*j + gate
#define KIN     1154
#define KW      1152          // GEMM K = [u(128) | h(1024)]  (x handled rank-2)
#define BK      64
#define NIT     18            // K tiles of 64
#define MHU     1.5f

// smem stage layout (bytes), row stride 144 (conflict-free LDSM):
//   Ahi [0, 9216)  Alo [9216, 18432)  W [18432, 36864)
#define ROWB    144
#define OFF_ALO 9216
#define OFF_W   18432
#define STG_B   36864

__device__ __align__(16) __half g_W  [NG * KW];
__device__ __align__(16) float  g_Wx [NG * 2];
__device__ __align__(16) float  g_bint[NG];
__device__ __align__(16) __half g_Ahi[2 * BATCH * KW];
__device__ __align__(16) __half g_Alo[2 * BATCH * KW];
__device__ __align__(16) float  g_c[BATCH * HIDDEN];
__device__ __align__(16) float  g_x[2 * BATCH * 2];
__device__ __align__(16) float4 g_part[2 * 4 * 64 * 32]; // [p][grp][row][nblk]

__device__ __forceinline__ float sigf(float x) {
    return __fdividef(1.f, 1.f + __expf(-x));
}
__device__ __forceinline__ float tanhfast(float x) {
    return 2.f * sigf(2.f * x) - 1.f;
}
__device__ __forceinline__ void h16split(float v, __half* hi, __half* lo) {
    __half h = __float2half(v);
    *hi = h;
    *lo = __float2half(v - __half2float(h));
}
__device__ __forceinline__ void mma16816(float* c, const uint32_t* a, const uint32_t* b) {
    asm volatile(
        "mma.sync.aligned.m16n8k16.row.col.f32.f16.f16.f32 "
        "{%0,%1,%2,%3}, {%4,%5,%6,%7}, {%8,%9}, {%0,%1,%2,%3};"
        : "+f"(c[0]), "+f"(c[1]), "+f"(c[2]), "+f"(c[3])
        : "r"(a[0]), "r"(a[1]), "r"(a[2]), "r"(a[3]), "r"(b[0]), "r"(b[1]));
}
__device__ __forceinline__ void ldsm4(uint32_t* r, uint32_t addr) {
    asm volatile(
        "ldmatrix.sync.aligned.m8n8.x4.shared.b16 {%0,%1,%2,%3}, [%4];"
        : "=r"(r[0]), "=r"(r[1]), "=r"(r[2]), "=r"(r[3]) : "r"(addr));
}
__device__ __forceinline__ void cpasync16(uint32_t dst, const void* src) {
    asm volatile("cp.async.cg.shared.global [%0], [%1], 16;" :: "r"(dst), "l"(src));
}

// ---------------------------------------------------------------------------
__global__ void repack(const float* __restrict__ WU_w, const float* __restrict__ WU_b) {
    int idx = blockIdx.x * blockDim.x + threadIdx.x;
    const int total = NG * KW;
    for (int i = idx; i < total; i += gridDim.x * blockDim.x) {
        int np = i / KW;
        int k2 = i - np * KW;
        int n  = (np & 3) * HIDDEN + (np >> 2);
        g_W[i] = __float2half(WU_w[(size_t)n * KIN + k2 + 2]);
    }
    if (idx < NG) {
        int n = (idx & 3) * HIDDEN + (idx >> 2);
        g_bint[idx] = WU_b[n];
        g_Wx[idx * 2 + 0] = WU_w[(size_t)n * KIN + 0];
        g_Wx[idx * 2 + 1] = WU_w[(size_t)n * KIN + 1];
    }
}

__global__ void init_state(const float* __restrict__ z0,
                           const float* __restrict__ c_z0,
                           const float* __restrict__ rnn_input) {
    int b = blockIdx.x, tid = threadIdx.x;
    for (int k = tid; k < KW; k += 256) {
        float v = (k < 128) ? rnn_input[(size_t)b * SEQ * INPUT + k]
                            : z0[b * ZS + 2 + (k - 128)];
        __half hi, lo;
        h16split(v, &hi, &lo);
        g_Ahi[(size_t)b * KW + k] = hi;
        g_Alo[(size_t)b * KW + k] = lo;
    }
    if (tid < 2) {
        float xv = z0[b * ZS + tid];
        g_x[b * 2 + tid] = xv;
        g_x[BATCH * 2 + b * 2 + tid] = xv;
    }
    for (int j = tid; j < HIDDEN; j += 256)
        g_c[b * HIDDEN + j] = c_z0[b * ZS + 2 + j];
}

// ---------------------------------------------------------------------------
// Per-step kernel: 128 CTAs = 4 grp(64 rows) x 32 nblk(128 gate cols),
// 512 threads / 16 warps (4 per SMSP). Warp tile 16x32 (1 m16, 4 n8).
// BK=64 (18 iters), 3-stage cp.async ring, ldmatrix, 2-product fp16 mma.
// ---------------------------------------------------------------------------
__global__ void __launch_bounds__(512) step_kernel(
    const float* __restrict__ rnn_input, const float* __restrict__ tau,
    const float* __restrict__ alpha_w,   const float* __restrict__ alpha_b,
    const float* __restrict__ Whx_w,     const float* __restrict__ Whx_b,
    float* __restrict__ out, int t)
{
    extern __shared__ __align__(16) unsigned char dynsm[];   // 3*STG_B
    __shared__ __align__(16) float4 partsm[64][4];
    __shared__ float2 s_wx[128];
    __shared__ float2 s_x[64];

    const int tid  = threadIdx.x;
    const int grp  = blockIdx.x >> 5;
    const int nblk = blockIdx.x & 31;
    const int m0   = grp * 64;
    const int n0   = nblk * 128;
    const int lane = tid & 31, wid = tid >> 5;
    const int warp_m = wid >> 2, warp_n = wid & 3;   // 4x4 warp grid
    const int r = lane >> 2, q = lane & 3;
    const int p  = t & 1;
    const int pn = p ^ 1;

    if (tid < 128)
        s_wx[tid] = make_float2(g_Wx[(n0 + tid) * 2], g_Wx[(n0 + tid) * 2 + 1]);

    // ---- staging: 4 cp.async16 per thread per stage (2048 slots / 512) ----
    const uint32_t smb = (uint32_t)__cvta_generic_to_shared(dynsm);
    const int arow  = tid >> 3, ach = tid & 7;          // 0..63
    const int wrow1 = (tid + 512) >> 3;                 // 64..127
    const __half* srcAh = g_Ahi + (size_t)p * BATCH * KW + (size_t)m0 * KW;
    const __half* srcAl = g_Alo + (size_t)p * BATCH * KW + (size_t)m0 * KW;
    const __half* srcW  = g_W + (size_t)n0 * KW;

    #define STG(it_) do {                                                        \
        const int _it = (it_);                                                   \
        const uint32_t _d = smb + (uint32_t)(_it % 3) * STG_B;                   \
        const int _kb = _it * 128;  /* bytes along K */                          \
        cpasync16(_d + arow * ROWB + ach * 16,                                   \
                  (const char*)(srcAh + (size_t)arow * KW) + _kb + ach * 16);    \
        cpasync16(_d + OFF_ALO + arow * ROWB + ach * 16,                         \
                  (const char*)(srcAl + (size_t)arow * KW) + _kb + ach * 16);    \
        cpasync16(_d + OFF_W + arow * ROWB + ach * 16,                           \
                  (const char*)(srcW + (size_t)arow * KW) + _kb + ach * 16);     \
        cpasync16(_d + OFF_W + wrow1 * ROWB + ach * 16,                          \
                  (const char*)(srcW + (size_t)wrow1 * KW) + _kb + ach * 16);    \
        asm volatile("cp.async.commit_group;" ::: "memory");                     \
    } while (0)

    STG(0);
    STG(1);

    // ---- per-lane ldmatrix offsets (bytes within stage) ----
    const int aRow = warp_m * 16 + (lane & 7) + ((lane >> 3) & 1) * 8;
    const uint32_t aOff = (uint32_t)(aRow * ROWB + (lane >> 4) * 16);
    const int bRow = warp_n * 32 + (lane & 7) + ((lane >> 4) & 1) * 8;
    const uint32_t bOff = (uint32_t)(OFF_W + bRow * ROWB + ((lane >> 3) & 1) * 16);

    float acc[4][4] = {};

    #pragma unroll 1
    for (int it = 0; it < NIT; it++) {
        if (it < NIT - 1) asm volatile("cp.async.wait_group 1;" ::: "memory");
        else              asm volatile("cp.async.wait_group 0;" ::: "memory");
        __syncthreads();
        if (it + 2 < NIT) STG(it + 2);

        const uint32_t S = smb + (uint32_t)(it % 3) * STG_B;
        const uint32_t aBase = S + aOff;
        const uint32_t bBase = S + bOff;

        #pragma unroll
        for (int c = 0; c < 4; c++) {
            const uint32_t kb = c * 32;   // 16 halves per chunk
            uint32_t ah[4], al[4], bw0[4], bw1[4];
            ldsm4(ah, aBase + kb);
            ldsm4(al, aBase + OFF_ALO + kb);
            ldsm4(bw0, bBase + kb);
            ldsm4(bw1, bBase + 16 * ROWB + kb);
            mma16816(acc[0], ah, bw0 + 0);
            mma16816(acc[0], al, bw0 + 0);
            mma16816(acc[1], ah, bw0 + 2);
            mma16816(acc[1], al, bw0 + 2);
            mma16816(acc[2], ah, bw1 + 0);
            mma16816(acc[2], al, bw1 + 0);
            mma16816(acc[3], ah, bw1 + 2);
            mma16816(acc[3], al, bw1 + 2);
        }
    }

    // ---------------- phase A: x_t from prev-step parts ----------------
    {
        const float4* pp = g_part + (size_t)(pn * 4 + grp) * 64 * 32;
        #pragma unroll 1
        for (int rr = 0; rr < 4; rr++) {
            const int row = wid * 4 + rr;
            const int b = m0 + row;
            float x0, x1;
            if (t == 0) {
                if (lane == 0) {
                    x0 = g_x[BATCH * 2 + b * 2];
                    x1 = g_x[BATCH * 2 + b * 2 + 1];
                }
            } else {
                float4 v = __ldcg(pp + row * 32 + lane);
                #pragma unroll
                for (int off = 16; off > 0; off >>= 1) {
                    v.x += __shfl_xor_sync(0xffffffffu, v.x, off);
                    v.y += __shfl_xor_sync(0xffffffffu, v.y, off);
                    v.z += __shfl_xor_sync(0xffffffffu, v.z, off);
                    v.w += __shfl_xor_sync(0xffffffffu, v.w, off);
                }
                if (lane == 0) {
                    float al0 = sigf(v.x + alpha_b[0]);
                    float al1 = sigf(v.y + alpha_b[1]);
                    float hx0 = v.z + Whx_b[0];
                    float hx1 = v.w + Whx_b[1];
                    float xp0 = g_x[pn * BATCH * 2 + b * 2];
                    float xp1 = g_x[pn * BATCH * 2 + b * 2 + 1];
                    float tv = tau[(size_t)b * SEQ + (t - 1)];
                    float xm0 = (1.f + tv * MHU) * xp0 - (tv * MHU) * xp1;
                    float xm1 = tv * (1.f / MHU) * xp0 + xp1;
                    x0 = al0 * xm0 + (1.f - al0) * hx0;
                    x1 = al1 * xm1 + (1.f - al1) * hx1;
                }
            }
            if (lane == 0) {
                s_x[row] = make_float2(x0, x1);
                if (nblk == 0) {
                    g_x[p * BATCH * 2 + b * 2]     = x0;
                    g_x[p * BATCH * 2 + b * 2 + 1] = x1;
                    if (t > 0) {
                        float* prow = out + ((size_t)b * SEQ + (t - 1)) * ZS;
                        prow[0] = x0;
                        prow[1] = x1;
                    }
                }
            }
        }
    }
    __syncthreads();

    // ---------------- phase B: LSTM gates + dots ----------------
    const size_t A1 = (size_t)pn * BATCH * KW;
    const int parity = q & 1;
    const int jj = q >> 1;
    {
        float d0 = 0.f, d1 = 0.f, d2 = 0.f, d3 = 0.f;
        const int row_blk = warp_m * 16 + r + parity * 8;
        const int b = m0 + row_blk;
        const float2 xv = s_x[row_blk];
        #pragma unroll
        for (int j = 0; j < 4; j++) {
            float c0 = acc[j][0], c1 = acc[j][1], c2 = acc[j][2], c3 = acc[j][3];
            float p0 = __shfl_xor_sync(0xffffffffu, c0, 1);
            float p1 = __shfl_xor_sync(0xffffffffu, c1, 1);
            float p2 = __shfl_xor_sync(0xffffffffu, c2, 1);
            float p3 = __shfl_xor_sync(0xffffffffu, c3, 1);
            float gi, gf, gg, go;
            if (!parity) { gi = c0; gf = c1; gg = p0; go = p1; }
            else         { gi = p2; gf = p3; gg = c2; go = c3; }
            const int jgl = warp_n * 8 + j * 2 + jj;       // local hidden idx
            const int jg  = (n0 >> 2) + jgl;               // global hidden idx
            const int npl = 4 * jgl;
            float4 bv = *(const float4*)(g_bint + 4 * jg);
            gi += bv.x + xv.x * s_wx[npl + 0].x + xv.y * s_wx[npl + 0].y;
            gf += bv.y + xv.x * s_wx[npl + 1].x + xv.y * s_wx[npl + 1].y;
            gg += bv.z + xv.x * s_wx[npl + 2].x + xv.y * s_wx[npl + 2].y;
            go += bv.w + xv.x * s_wx[npl + 3].x + xv.y * s_wx[npl + 3].y;
            float co = g_c[b * HIDDEN + jg];
            float cn = sigf(gf) * co + sigf(gi) * tanhfast(gg);
            float h  = sigf(go) * tanhfast(cn);
            g_c[b * HIDDEN + jg] = cn;
            out[((size_t)b * SEQ + t) * ZS + 2 + jg] = h;
            __half hh, hl;
            h16split(h, &hh, &hl);
            g_Ahi[A1 + (size_t)b * KW + 128 + jg] = hh;
            g_Alo[A1 + (size_t)b * KW + 128 + jg] = hl;
            d0 += h * alpha_w[jg];
            d1 += h * alpha_w[HIDDEN + jg];
            d2 += h * Whx_w[jg];
            d3 += h * Whx_w[HIDDEN + jg];
        }
        d0 += __shfl_xor_sync(0xffffffffu, d0, 2);
        d1 += __shfl_xor_sync(0xffffffffu, d1, 2);
        d2 += __shfl_xor_sync(0xffffffffu, d2, 2);
        d3 += __shfl_xor_sync(0xffffffffu, d3, 2);
        if (q < 2) partsm[row_blk][warp_n] = make_float4(d0, d1, d2, d3);
    }
    __syncthreads();
    if (tid < 64) {
        float4 a = partsm[tid][0], bb = partsm[tid][1],
               c = partsm[tid][2], d = partsm[tid][3];
        float4 s = make_float4(a.x + bb.x + c.x + d.x, a.y + bb.y + c.y + d.y,
                               a.z + bb.z + c.z + d.z, a.w + bb.w + c.w + d.w);
        g_part[((size_t)(p * 4 + grp) * 64 + tid) * 32 + nblk] = s;
    }

    // stage u_{t+1}: this CTA covers 2 of the 64 rows (threads 0-255)
    if (t + 1 < SEQ && tid < 256) {
        int row = 2 * nblk + (tid >> 7);
        int col = tid & 127;
        int b = m0 + row;
        float u = rnn_input[((size_t)b * SEQ + (t + 1)) * INPUT + col];
        __half hi, lo;
        h16split(u, &hi, &lo);
        g_Ahi[A1 + (size_t)b * KW + col] = hi;
        g_Alo[A1 + (size_t)b * KW + col] = lo;
    }
}

// ---------------------------------------------------------------------------
__global__ void finalize(const float* __restrict__ tau,
                         const float* __restrict__ alpha_b, const float* __restrict__ Whx_b,
                         const float* __restrict__ c_z0, float* __restrict__ out) {
    int b = blockIdx.x, tid = threadIdx.x;
    __shared__ float2 s_xf;
    if (tid < 32) {
        const float4* pp = g_part + (size_t)(1 * 4 + (b >> 6)) * 64 * 32 + (size_t)(b & 63) * 32;
        float4 v = __ldcg(pp + tid);
        #pragma unroll
        for (int off = 16; off > 0; off >>= 1) {
            v.x += __shfl_xor_sync(0xffffffffu, v.x, off);
            v.y += __shfl_xor_sync(0xffffffffu, v.y, off);
            v.z += __shfl_xor_sync(0xffffffffu, v.z, off);
            v.w += __shfl_xor_sync(0xffffffffu, v.w, off);
        }
        if (tid == 0) {
            float al0 = sigf(v.x + alpha_b[0]);
            float al1 = sigf(v.y + alpha_b[1]);
            float hx0 = v.z + Whx_b[0];
            float hx1 = v.w + Whx_b[1];
            float xp0 = g_x[BATCH * 2 + b * 2];       // parity 1 = step 255
            float xp1 = g_x[BATCH * 2 + b * 2 + 1];
            float tv = tau[(size_t)b * SEQ + (SEQ - 1)];
            float xm0 = (1.f + tv * MHU) * xp0 - (tv * MHU) * xp1;
            float xm1 = tv * (1.f / MHU) * xp0 + xp1;
            float x0 = al0 * xm0 + (1.f - al0) * hx0;
            float x1 = al1 * xm1 + (1.f - al1) * hx1;
            float* prow = out + ((size_t)b * SEQ + (SEQ - 1)) * ZS;
            prow[0] = x0; prow[1] = x1;
            s_xf = make_float2(x0, x1);
        }
    }
    __syncthreads();
    size_t base = (size_t)BATCH * SEQ * ZS;
    float* zf  = out + base + (size_t)b * ZS;
    float* czf = out + base + (size_t)BATCH * ZS + (size_t)b * ZS;
    const float* last = out + ((size_t)b * SEQ + (SEQ - 1)) * ZS;
    for (int k = tid; k < ZS; k += 256) {
        zf[k]  = (k == 0) ? s_xf.x : (k == 1) ? s_xf.y : last[k];
        czf[k] = (k < 2) ? c_z0[b * ZS + k] : g_c[(size_t)b * HIDDEN + (k - 2)];
    }
}

// ---------------------------------------------------------------------------
extern "C" void kernel_launch(void* const* d_in, const int* in_sizes, int n_in,
                              void* d_out, int out_size) {
    const float* rnn_input = (const float*)d_in[0];
    const float* tau       = (const float*)d_in[1];
    const float* z0        = (const float*)d_in[2];
    const float* c_z0      = (const float*)d_in[3];
    const float* WU_w      = (const float*)d_in[4];
    const float* WU_b      = (const float*)d_in[5];
    const float* alpha_w   = (const float*)d_in[6];
    const float* alpha_b   = (const float*)d_in[7];
    const float* Whx_w     = (const float*)d_in[8];
    const float* Whx_b     = (const float*)d_in[9];
    float* out = (float*)d_out;

    static bool attr_set = false;
    if (!attr_set) {
        cudaFuncSetAttribute(step_kernel, cudaFuncAttributeMaxDynamicSharedMemorySize,
                             3 * STG_B);
        attr_set = true;
    }

    repack<<<4096, 256>>>(WU_w, WU_b);
    init_state<<<BATCH, 256>>>(z0, c_z0, rnn_input);
    for (int t = 0; t < SEQ; t++) {
        step_kernel<<<128, 512, 3 * STG_B>>>(rnn_input, tau, alpha_w, alpha_b,
                                             Whx_w, Whx_b, out, t);
    }
    finalize<<<BATCH, 256>>>(tau, alpha_b, Whx_b, c_z0, out);
}

// round 11
// speedup vs baseline: 1.9131x; 1.0129x over previous
#include <cuda_runtime.h>
#include <cuda_fp16.h>
#include <math.h>
#include <stdint.h>

#define BATCH   256
#define SEQ     256
#define INPUT   128
#define HIDDEN  1024
#define ZS      1026
#define NG      4096          // 4*HIDDEN interleaved: col n' = 4*j + gate
#define KIN     1154
#define KW      1152          // GEMM K = [u(128) | h(1024)]  (x handled rank-2)
#define BK      64
#define NIT     18            // K tiles of 64
#define MHU     1.5f

// smem stage layout (bytes), row stride 144 (conflict-free LDSM):
//   Ahi [0, 9216)  Alo [9216, 18432)  W [18432, 36864)
#define ROWB    144
#define OFF_ALO 9216
#define OFF_W   18432
#define STG_B   36864

__device__ __align__(16) __half g_W  [NG * KW];
__device__ __align__(16) float  g_Wx [NG * 2];
__device__ __align__(16) float  g_bint[NG];
__device__ __align__(16) __half g_Ahi[2 * BATCH * KW];
__device__ __align__(16) __half g_Alo[2 * BATCH * KW];
__device__ __align__(16) float  g_c[BATCH * HIDDEN];
__device__ __align__(16) float  g_x[2 * BATCH * 2];
__device__ __align__(16) float4 g_part[2 * 4 * 64 * 32]; // [p][grp][row][nblk]

__device__ __forceinline__ float sigf(float x) {
    return __fdividef(1.f, 1.f + __expf(-x));
}
__device__ __forceinline__ float tanhfast(float x) {
    return 2.f * sigf(2.f * x) - 1.f;
}
__device__ __forceinline__ void h16split(float v, __half* hi, __half* lo) {
    __half h = __float2half(v);
    *hi = h;
    *lo = __float2half(v - __half2float(h));
}
__device__ __forceinline__ void mma16816(float* c, const uint32_t* a, const uint32_t* b) {
    asm volatile(
        "mma.sync.aligned.m16n8k16.row.col.f32.f16.f16.f32 "
        "{%0,%1,%2,%3}, {%4,%5,%6,%7}, {%8,%9}, {%0,%1,%2,%3};"
        : "+f"(c[0]), "+f"(c[1]), "+f"(c[2]), "+f"(c[3])
        : "r"(a[0]), "r"(a[1]), "r"(a[2]), "r"(a[3]), "r"(b[0]), "r"(b[1]));
}
__device__ __forceinline__ void ldsm4(uint32_t* r, uint32_t addr) {
    asm volatile(
        "ldmatrix.sync.aligned.m8n8.x4.shared.b16 {%0,%1,%2,%3}, [%4];"
        : "=r"(r[0]), "=r"(r[1]), "=r"(r[2]), "=r"(r[3]) : "r"(addr));
}
__device__ __forceinline__ void cpasync16(uint32_t dst, const void* src) {
    asm volatile("cp.async.cg.shared.global [%0], [%1], 16;" :: "r"(dst), "l"(src));
}

// ---------------------------------------------------------------------------
__global__ void repack(const float* __restrict__ WU_w, const float* __restrict__ WU_b) {
    int idx = blockIdx.x * blockDim.x + threadIdx.x;
    const int total = NG * KW;
    for (int i = idx; i < total; i += gridDim.x * blockDim.x) {
        int np = i / KW;
        int k2 = i - np * KW;
        int n  = (np & 3) * HIDDEN + (np >> 2);
        g_W[i] = __float2half(WU_w[(size_t)n * KIN + k2 + 2]);
    }
    if (idx < NG) {
        int n = (idx & 3) * HIDDEN + (idx >> 2);
        g_bint[idx] = WU_b[n];
        g_Wx[idx * 2 + 0] = WU_w[(size_t)n * KIN + 0];
        g_Wx[idx * 2 + 1] = WU_w[(size_t)n * KIN + 1];
    }
}

__global__ void init_state(const float* __restrict__ z0,
                           const float* __restrict__ c_z0,
                           const float* __restrict__ rnn_input) {
    int b = blockIdx.x, tid = threadIdx.x;
    for (int k = tid; k < KW; k += 256) {
        float v = (k < 128) ? rnn_input[(size_t)b * SEQ * INPUT + k]
                            : z0[b * ZS + 2 + (k - 128)];
        __half hi, lo;
        h16split(v, &hi, &lo);
        g_Ahi[(size_t)b * KW + k] = hi;
        g_Alo[(size_t)b * KW + k] = lo;
    }
    if (tid < 2) {
        float xv = z0[b * ZS + tid];
        g_x[b * 2 + tid] = xv;
        g_x[BATCH * 2 + b * 2 + tid] = xv;
    }
    for (int j = tid; j < HIDDEN; j += 256)
        g_c[b * HIDDEN + j] = c_z0[b * ZS + 2 + j];
}

// ---------------------------------------------------------------------------
// Per-step kernel: 128 CTAs = 4 grp(64 rows) x 32 nblk(128 gate cols),
// 1024 threads / 32 warps (8 per SMSP). Warp grid 4(m) x 8(n), tile 16x16.
// BK=64 (18 iters), 3-stage cp.async ring, ldmatrix, 2-product fp16 mma.
// ---------------------------------------------------------------------------
__global__ void __launch_bounds__(1024) step_kernel(
    const float* __restrict__ rnn_input, const float* __restrict__ tau,
    const float* __restrict__ alpha_w,   const float* __restrict__ alpha_b,
    const float* __restrict__ Whx_w,     const float* __restrict__ Whx_b,
    float* __restrict__ out, int t)
{
    extern __shared__ __align__(16) unsigned char dynsm[];   // 3*STG_B
    __shared__ __align__(16) float4 partsm[64][8];
    __shared__ float2 s_wx[128];
    __shared__ float2 s_x[64];

    const int tid  = threadIdx.x;
    const int grp  = blockIdx.x >> 5;
    const int nblk = blockIdx.x & 31;
    const int m0   = grp * 64;
    const int n0   = nblk * 128;
    const int lane = tid & 31, wid = tid >> 5;
    const int warp_m = wid >> 3, warp_n = wid & 7;   // 4x8 warp grid
    const int r = lane >> 2, q = lane & 3;
    const int p  = t & 1;
    const int pn = p ^ 1;

    if (tid < 128)
        s_wx[tid] = make_float2(g_Wx[(n0 + tid) * 2], g_Wx[(n0 + tid) * 2 + 1]);

    // ---- staging: 2 cp.async16 per thread per stage (2048 slots / 1024) ----
    const uint32_t smb = (uint32_t)__cvta_generic_to_shared(dynsm);
    const int wrow = tid >> 3, wch = tid & 7;           // W row 0..127
    const int aslot = tid & 511;
    const int arow = aslot >> 3, ach = aslot & 7;       // A row 0..63
    const uint32_t aRegOff = (tid < 512) ? 0u : (uint32_t)OFF_ALO;
    const __half* srcAh = g_Ahi + (size_t)p * BATCH * KW + (size_t)m0 * KW;
    const __half* srcAl = g_Alo + (size_t)p * BATCH * KW + (size_t)m0 * KW;
    const __half* srcA  = (tid < 512) ? srcAh : srcAl;
    const __half* srcW  = g_W + (size_t)n0 * KW;

    #define STG(it_) do {                                                        \
        const int _it = (it_);                                                   \
        const uint32_t _d = smb + (uint32_t)(_it % 3) * STG_B;                   \
        const int _kb = _it * 128;  /* bytes along K */                          \
        cpasync16(_d + aRegOff + arow * ROWB + ach * 16,                         \
                  (const char*)(srcA + (size_t)arow * KW) + _kb + ach * 16);     \
        cpasync16(_d + OFF_W + wrow * ROWB + wch * 16,                           \
                  (const char*)(srcW + (size_t)wrow * KW) + _kb + wch * 16);     \
        asm volatile("cp.async.commit_group;" ::: "memory");                     \
    } while (0)

    STG(0);
    STG(1);

    // ---- per-lane ldmatrix offsets (bytes within stage) ----
    const int aRow = warp_m * 16 + (lane & 7) + ((lane >> 3) & 1) * 8;
    const uint32_t aOff = (uint32_t)(aRow * ROWB + (lane >> 4) * 16);
    const int bRow = warp_n * 16 + (lane & 7) + ((lane >> 4) & 1) * 8;
    const uint32_t bOff = (uint32_t)(OFF_W + bRow * ROWB + ((lane >> 3) & 1) * 16);

    float acc[2][4] = {};

    #pragma unroll 1
    for (int it = 0; it < NIT; it++) {
        if (it < NIT - 1) asm volatile("cp.async.wait_group 1;" ::: "memory");
        else              asm volatile("cp.async.wait_group 0;" ::: "memory");
        __syncthreads();
        if (it + 2 < NIT) STG(it + 2);

        const uint32_t S = smb + (uint32_t)(it % 3) * STG_B;
        const uint32_t aBase = S + aOff;
        const uint32_t bBase = S + bOff;

        #pragma unroll
        for (int c = 0; c < 4; c++) {
            const uint32_t kb = c * 32;   // 16 halves per chunk
            uint32_t ah[4], al[4], bw[4];
            ldsm4(ah, aBase + kb);
            ldsm4(al, aBase + OFF_ALO + kb);
            ldsm4(bw, bBase + kb);
            mma16816(acc[0], ah, bw + 0);
            mma16816(acc[0], al, bw + 0);
            mma16816(acc[1], ah, bw + 2);
            mma16816(acc[1], al, bw + 2);
        }
    }

    // ---------------- phase A: x_t from prev-step parts ----------------
    {
        const float4* pp = g_part + (size_t)(pn * 4 + grp) * 64 * 32;
        #pragma unroll 1
        for (int rr = 0; rr < 2; rr++) {
            const int row = wid * 2 + rr;
            const int b = m0 + row;
            float x0, x1;
            if (t == 0) {
                if (lane == 0) {
                    x0 = g_x[BATCH * 2 + b * 2];
                    x1 = g_x[BATCH * 2 + b * 2 + 1];
                }
            } else {
                float4 v = __ldcg(pp + row * 32 + lane);
                #pragma unroll
                for (int off = 16; off > 0; off >>= 1) {
                    v.x += __shfl_xor_sync(0xffffffffu, v.x, off);
                    v.y += __shfl_xor_sync(0xffffffffu, v.y, off);
                    v.z += __shfl_xor_sync(0xffffffffu, v.z, off);
                    v.w += __shfl_xor_sync(0xffffffffu, v.w, off);
                }
                if (lane == 0) {
                    float al0 = sigf(v.x + alpha_b[0]);
                    float al1 = sigf(v.y + alpha_b[1]);
                    float hx0 = v.z + Whx_b[0];
                    float hx1 = v.w + Whx_b[1];
                    float xp0 = g_x[pn * BATCH * 2 + b * 2];
                    float xp1 = g_x[pn * BATCH * 2 + b * 2 + 1];
                    float tv = tau[(size_t)b * SEQ + (t - 1)];
                    float xm0 = (1.f + tv * MHU) * xp0 - (tv * MHU) * xp1;
                    float xm1 = tv * (1.f / MHU) * xp0 + xp1;
                    x0 = al0 * xm0 + (1.f - al0) * hx0;
                    x1 = al1 * xm1 + (1.f - al1) * hx1;
                }
            }
            if (lane == 0) {
                s_x[row] = make_float2(x0, x1);
                if (nblk == 0) {
                    g_x[p * BATCH * 2 + b * 2]     = x0;
                    g_x[p * BATCH * 2 + b * 2 + 1] = x1;
                    if (t > 0) {
                        float* prow = out + ((size_t)b * SEQ + (t - 1)) * ZS;
                        prow[0] = x0;
                        prow[1] = x1;
                    }
                }
            }
        }
    }
    __syncthreads();

    // ---------------- phase B: LSTM gates + dots ----------------
    const size_t A1 = (size_t)pn * BATCH * KW;
    const int parity = q & 1;
    const int jj = q >> 1;
    {
        float d0 = 0.f, d1 = 0.f, d2 = 0.f, d3 = 0.f;
        const int row_blk = warp_m * 16 + r + parity * 8;
        const int b = m0 + row_blk;
        const float2 xv = s_x[row_blk];
        #pragma unroll
        for (int j = 0; j < 2; j++) {
            float c0 = acc[j][0], c1 = acc[j][1], c2 = acc[j][2], c3 = acc[j][3];
            float p0 = __shfl_xor_sync(0xffffffffu, c0, 1);
            float p1 = __shfl_xor_sync(0xffffffffu, c1, 1);
            float p2 = __shfl_xor_sync(0xffffffffu, c2, 1);
            float p3 = __shfl_xor_sync(0xffffffffu, c3, 1);
            float gi, gf, gg, go;
            if (!parity) { gi = c0; gf = c1; gg = p0; go = p1; }
            else         { gi = p2; gf = p3; gg = c2; go = c3; }
            const int jgl = warp_n * 4 + j * 2 + jj;       // local hidden idx 0..31
            const int jg  = (n0 >> 2) + jgl;               // global hidden idx
            const int npl = 4 * jgl;
            float4 bv = *(const float4*)(g_bint + 4 * jg);
            gi += bv.x + xv.x * s_wx[npl + 0].x + xv.y * s_wx[npl + 0].y;
            gf += bv.y + xv.x * s_wx[npl + 1].x + xv.y * s_wx[npl + 1].y;
            gg += bv.z + xv.x * s_wx[npl + 2].x + xv.y * s_wx[npl + 2].y;
            go += bv.w + xv.x * s_wx[npl + 3].x + xv.y * s_wx[npl + 3].y;
            float co = g_c[b * HIDDEN + jg];
            float cn = sigf(gf) * co + sigf(gi) * tanhfast(gg);
            float h  = sigf(go) * tanhfast(cn);
            g_c[b * HIDDEN + jg] = cn;
            out[((size_t)b * SEQ + t) * ZS + 2 + jg] = h;
            __half hh, hl;
            h16split(h, &hh, &hl);
            g_Ahi[A1 + (size_t)b * KW + 128 + jg] = hh;
            g_Alo[A1 + (size_t)b * KW + 128 + jg] = hl;
            d0 += h * alpha_w[jg];
            d1 += h * alpha_w[HIDDEN + jg];
            d2 += h * Whx_w[jg];
            d3 += h * Whx_w[HIDDEN + jg];
        }
        d0 += __shfl_xor_sync(0xffffffffu, d0, 2);
        d1 += __shfl_xor_sync(0xffffffffu, d1, 2);
        d2 += __shfl_xor_sync(0xffffffffu, d2, 2);
        d3 += __shfl_xor_sync(0xffffffffu, d3, 2);
        if (q < 2) partsm[row_blk][warp_n] = make_float4(d0, d1, d2, d3);
    }
    __syncthreads();
    if (tid < 64) {
        float4 s = partsm[tid][0];
        #pragma unroll
        for (int w = 1; w < 8; w++) {
            float4 v = partsm[tid][w];
            s.x += v.x; s.y += v.y; s.z += v.z; s.w += v.w;
        }
        g_part[((size_t)(p * 4 + grp) * 64 + tid) * 32 + nblk] = s;
    }

    // stage u_{t+1}: this CTA covers 2 of the 64 rows (threads 0-255)
    if (t + 1 < SEQ && tid < 256) {
        int row = 2 * nblk + (tid >> 7);
        int col = tid & 127;
        int b = m0 + row;
        float u = rnn_input[((size_t)b * SEQ + (t + 1)) * INPUT + col];
        __half hi, lo;
        h16split(u, &hi, &lo);
        g_Ahi[A1 + (size_t)b * KW + col] = hi;
        g_Alo[A1 + (size_t)b * KW + col] = lo;
    }
}

// ---------------------------------------------------------------------------
__global__ void finalize(const float* __restrict__ tau,
                         const float* __restrict__ alpha_b, const float* __restrict__ Whx_b,
                         const float* __restrict__ c_z0, float* __restrict__ out) {
    int b = blockIdx.x, tid = threadIdx.x;
    __shared__ float2 s_xf;
    if (tid < 32) {
        const float4* pp = g_part + (size_t)(1 * 4 + (b >> 6)) * 64 * 32 + (size_t)(b & 63) * 32;
        float4 v = __ldcg(pp + tid);
        #pragma unroll
        for (int off = 16; off > 0; off >>= 1) {
            v.x += __shfl_xor_sync(0xffffffffu, v.x, off);
            v.y += __shfl_xor_sync(0xffffffffu, v.y, off);
            v.z += __shfl_xor_sync(0xffffffffu, v.z, off);
            v.w += __shfl_xor_sync(0xffffffffu, v.w, off);
        }
        if (tid == 0) {
            float al0 = sigf(v.x + alpha_b[0]);
            float al1 = sigf(v.y + alpha_b[1]);
            float hx0 = v.z + Whx_b[0];
            float hx1 = v.w + Whx_b[1];
            float xp0 = g_x[BATCH * 2 + b * 2];       // parity 1 = step 255
            float xp1 = g_x[BATCH * 2 + b * 2 + 1];
            float tv = tau[(size_t)b * SEQ + (SEQ - 1)];
            float xm0 = (1.f + tv * MHU) * xp0 - (tv * MHU) * xp1;
            float xm1 = tv * (1.f / MHU) * xp0 + xp1;
            float x0 = al0 * xm0 + (1.f - al0) * hx0;
            float x1 = al1 * xm1 + (1.f - al1) * hx1;
            float* prow = out + ((size_t)b * SEQ + (SEQ - 1)) * ZS;
            prow[0] = x0; prow[1] = x1;
            s_xf = make_float2(x0, x1);
        }
    }
    __syncthreads();
    size_t base = (size_t)BATCH * SEQ * ZS;
    float* zf  = out + base + (size_t)b * ZS;
    float* czf = out + base + (size_t)BATCH * ZS + (size_t)b * ZS;
    const float* last = out + ((size_t)b * SEQ + (SEQ - 1)) * ZS;
    for (int k = tid; k < ZS; k += 256) {
        zf[k]  = (k == 0) ? s_xf.x : (k == 1) ? s_xf.y : last[k];
        czf[k] = (k < 2) ? c_z0[b * ZS + k] : g_c[(size_t)b * HIDDEN + (k - 2)];
    }
}

// ---------------------------------------------------------------------------
extern "C" void kernel_launch(void* const* d_in, const int* in_sizes, int n_in,
                              void* d_out, int out_size) {
    const float* rnn_input = (const float*)d_in[0];
    const float* tau       = (const float*)d_in[1];
    const float* z0        = (const float*)d_in[2];
    const float* c_z0      = (const float*)d_in[3];
    const float* WU_w      = (const float*)d_in[4];
    const float* WU_b      = (const float*)d_in[5];
    const float* alpha_w   = (const float*)d_in[6];
    const float* alpha_b   = (const float*)d_in[7];
    const float* Whx_w     = (const float*)d_in[8];
    const float* Whx_b     = (const float*)d_in[9];
    float* out = (float*)d_out;

    static bool attr_set = false;
    if (!attr_set) {
        cudaFuncSetAttribute(step_kernel, cudaFuncAttributeMaxDynamicSharedMemorySize,
                             3 * STG_B);
        attr_set = true;
    }

    repack<<<4096, 256>>>(WU_w, WU_b);
    init_state<<<BATCH, 256>>>(z0, c_z0, rnn_input);
    for (int t = 0; t < SEQ; t++) {
        step_kernel<<<128, 1024, 3 * STG_B>>>(rnn_input, tau, alpha_w, alpha_b,
                                              Whx_w, Whx_b, out, t);
    }
    finalize<<<BATCH, 256>>>(tau, alpha_b, Whx_b, c_z0, out);
}

// round 12
// speedup vs baseline: 1.9421x; 1.0151x over previous
#include <cuda_runtime.h>
#include <cuda_fp16.h>
#include <math.h>
#include <stdint.h>

#define BATCH   256
#define SEQ     256
#define INPUT   128
#define HIDDEN  1024
#define ZS      1026
#define NG      4096          // 4*HIDDEN interleaved: col n' = 4*j + gate
#define KIN     1154
#define KW      1152          // GEMM K = [u(128) | h(1024)]  (x handled rank-2)
#define BK      128
#define NIT     9             // K tiles of 128
#define MHU     1.5f

// smem stage layout (bytes), row stride 272 (BK=128 row = 256B + 16 pad;
// 272 = 68 words, 68 mod 32 = 4 -> same conflict-free LDSM phase as before):
//   Ahi [0, 17408)  Alo [17408, 34816)  W [34816, 69632)
#define ROWB    272
#define OFF_ALO 17408
#define OFF_W   34816
#define STG_B   69632

__device__ __align__(16) __half g_W  [NG * KW];
__device__ __align__(16) float  g_Wx [NG * 2];
__device__ __align__(16) float  g_bint[NG];
__device__ __align__(16) __half g_Ahi[2 * BATCH * KW];
__device__ __align__(16) __half g_Alo[2 * BATCH * KW];
__device__ __align__(16) float  g_c[BATCH * HIDDEN];
__device__ __align__(16) float  g_x[2 * BATCH * 2];
__device__ __align__(16) float4 g_part[2 * 4 * 64 * 32]; // [p][grp][row][nblk]

__device__ __forceinline__ float sigf(float x) {
    return __fdividef(1.f, 1.f + __expf(-x));
}
__device__ __forceinline__ float tanhfast(float x) {
    return 2.f * sigf(2.f * x) - 1.f;
}
__device__ __forceinline__ void h16split(float v, __half* hi, __half* lo) {
    __half h = __float2half(v);
    *hi = h;
    *lo = __float2half(v - __half2float(h));
}
__device__ __forceinline__ void mma16816(float* c, const uint32_t* a, const uint32_t* b) {
    asm volatile(
        "mma.sync.aligned.m16n8k16.row.col.f32.f16.f16.f32 "
        "{%0,%1,%2,%3}, {%4,%5,%6,%7}, {%8,%9}, {%0,%1,%2,%3};"
        : "+f"(c[0]), "+f"(c[1]), "+f"(c[2]), "+f"(c[3])
        : "r"(a[0]), "r"(a[1]), "r"(a[2]), "r"(a[3]), "r"(b[0]), "r"(b[1]));
}
__device__ __forceinline__ void ldsm4(uint32_t* r, uint32_t addr) {
    asm volatile(
        "ldmatrix.sync.aligned.m8n8.x4.shared.b16 {%0,%1,%2,%3}, [%4];"
        : "=r"(r[0]), "=r"(r[1]), "=r"(r[2]), "=r"(r[3]) : "r"(addr));
}
__device__ __forceinline__ void cpasync16(uint32_t dst, const void* src) {
    asm volatile("cp.async.cg.shared.global [%0], [%1], 16;" :: "r"(dst), "l"(src));
}

// ---------------------------------------------------------------------------
__global__ void repack(const float* __restrict__ WU_w, const float* __restrict__ WU_b) {
    int idx = blockIdx.x * blockDim.x + threadIdx.x;
    const int total = NG * KW;
    for (int i = idx; i < total; i += gridDim.x * blockDim.x) {
        int np = i / KW;
        int k2 = i - np * KW;
        int n  = (np & 3) * HIDDEN + (np >> 2);
        g_W[i] = __float2half(WU_w[(size_t)n * KIN + k2 + 2]);
    }
    if (idx < NG) {
        int n = (idx & 3) * HIDDEN + (idx >> 2);
        g_bint[idx] = WU_b[n];
        g_Wx[idx * 2 + 0] = WU_w[(size_t)n * KIN + 0];
        g_Wx[idx * 2 + 1] = WU_w[(size_t)n * KIN + 1];
    }
}

__global__ void init_state(const float* __restrict__ z0,
                           const float* __restrict__ c_z0,
                           const float* __restrict__ rnn_input) {
    int b = blockIdx.x, tid = threadIdx.x;
    for (int k = tid; k < KW; k += 256) {
        float v = (k < 128) ? rnn_input[(size_t)b * SEQ * INPUT + k]
                            : z0[b * ZS + 2 + (k - 128)];
        __half hi, lo;
        h16split(v, &hi, &lo);
        g_Ahi[(size_t)b * KW + k] = hi;
        g_Alo[(size_t)b * KW + k] = lo;
    }
    if (tid < 2) {
        float xv = z0[b * ZS + tid];
        g_x[b * 2 + tid] = xv;
        g_x[BATCH * 2 + b * 2 + tid] = xv;
    }
    for (int j = tid; j < HIDDEN; j += 256)
        g_c[b * HIDDEN + j] = c_z0[b * ZS + 2 + j];
}

// ---------------------------------------------------------------------------
// Per-step kernel: 128 CTAs = 4 grp(64 rows) x 32 nblk(128 gate cols),
// 1024 threads / 32 warps (8 per SMSP). Warp grid 4(m) x 8(n), tile 16x16.
// BK=128 (9 iters), 2-stage ping-pong cp.async ring, ldmatrix, fp16 mma.
// ---------------------------------------------------------------------------
__global__ void __launch_bounds__(1024) step_kernel(
    const float* __restrict__ rnn_input, const float* __restrict__ tau,
    const float* __restrict__ alpha_w,   const float* __restrict__ alpha_b,
    const float* __restrict__ Whx_w,     const float* __restrict__ Whx_b,
    float* __restrict__ out, int t)
{
    extern __shared__ __align__(16) unsigned char dynsm[];   // 2*STG_B
    __shared__ __align__(16) float4 partsm[64][8];
    __shared__ float2 s_wx[128];
    __shared__ float2 s_x[64];

    const int tid  = threadIdx.x;
    const int grp  = blockIdx.x >> 5;
    const int nblk = blockIdx.x & 31;
    const int m0   = grp * 64;
    const int n0   = nblk * 128;
    const int lane = tid & 31, wid = tid >> 5;
    const int warp_m = wid >> 3, warp_n = wid & 7;   // 4x8 warp grid
    const int r = lane >> 2, q = lane & 3;
    const int p  = t & 1;
    const int pn = p ^ 1;

    if (tid < 128)
        s_wx[tid] = make_float2(g_Wx[(n0 + tid) * 2], g_Wx[(n0 + tid) * 2 + 1]);

    // ---- staging: 4 cp.async16 per thread per stage (4096 slots / 1024) ----
    //   i=0: Ahi row=tid>>4 ch=tid&15 ; i=1: Alo same
    //   i=2: W rows 0..63 ; i=3: W rows 64..127
    const uint32_t smb = (uint32_t)__cvta_generic_to_shared(dynsm);
    const int srow = tid >> 4, sch = tid & 15;
    const __half* srcAh = g_Ahi + (size_t)p * BATCH * KW + (size_t)m0 * KW;
    const __half* srcAl = g_Alo + (size_t)p * BATCH * KW + (size_t)m0 * KW;
    const __half* srcW  = g_W + (size_t)n0 * KW;

    #define STG(it_) do {                                                        \
        const int _it = (it_);                                                   \
        const uint32_t _d = smb + (uint32_t)(_it & 1) * STG_B;                   \
        const int _kb = _it * 256;  /* bytes along K */                          \
        cpasync16(_d + srow * ROWB + sch * 16,                                   \
                  (const char*)(srcAh + (size_t)srow * KW) + _kb + sch * 16);    \
        cpasync16(_d + OFF_ALO + srow * ROWB + sch * 16,                         \
                  (const char*)(srcAl + (size_t)srow * KW) + _kb + sch * 16);    \
        cpasync16(_d + OFF_W + srow * ROWB + sch * 16,                           \
                  (const char*)(srcW + (size_t)srow * KW) + _kb + sch * 16);     \
        cpasync16(_d + OFF_W + (64 + srow) * ROWB + sch * 16,                    \
                  (const char*)(srcW + (size_t)(64 + srow) * KW) + _kb + sch * 16); \
        asm volatile("cp.async.commit_group;" ::: "memory");                     \
    } while (0)

    STG(0);

    // ---- per-lane ldmatrix offsets (bytes within stage) ----
    const int aRow = warp_m * 16 + (lane & 7) + ((lane >> 3) & 1) * 8;
    const uint32_t aOff = (uint32_t)(aRow * ROWB + (lane >> 4) * 16);
    const int bRow = warp_n * 16 + (lane & 7) + ((lane >> 4) & 1) * 8;
    const uint32_t bOff = (uint32_t)(OFF_W + bRow * ROWB + ((lane >> 3) & 1) * 16);

    float acc[2][4] = {};

    #pragma unroll 1
    for (int it = 0; it < NIT; it++) {
        asm volatile("cp.async.wait_group 0;" ::: "memory");
        __syncthreads();
        if (it + 1 < NIT) STG(it + 1);

        const uint32_t S = smb + (uint32_t)(it & 1) * STG_B;
        const uint32_t aBase = S + aOff;
        const uint32_t bBase = S + bOff;

        #pragma unroll
        for (int c = 0; c < 8; c++) {
            const uint32_t kb = c * 32;   // 16 halves per chunk
            uint32_t ah[4], al[4], bw[4];
            ldsm4(ah, aBase + kb);
            ldsm4(al, aBase + OFF_ALO + kb);
            ldsm4(bw, bBase + kb);
            mma16816(acc[0], ah, bw + 0);
            mma16816(acc[0], al, bw + 0);
            mma16816(acc[1], ah, bw + 2);
            mma16816(acc[1], al, bw + 2);
        }
    }

    // ---------------- phase A: x_t from prev-step parts ----------------
    {
        const float4* pp = g_part + (size_t)(pn * 4 + grp) * 64 * 32;
        #pragma unroll 1
        for (int rr = 0; rr < 2; rr++) {
            const int row = wid * 2 + rr;
            const int b = m0 + row;
            float x0, x1;
            if (t == 0) {
                if (lane == 0) {
                    x0 = g_x[BATCH * 2 + b * 2];
                    x1 = g_x[BATCH * 2 + b * 2 + 1];
                }
            } else {
                float4 v = __ldcg(pp + row * 32 + lane);
                #pragma unroll
                for (int off = 16; off > 0; off >>= 1) {
                    v.x += __shfl_xor_sync(0xffffffffu, v.x, off);
                    v.y += __shfl_xor_sync(0xffffffffu, v.y, off);
                    v.z += __shfl_xor_sync(0xffffffffu, v.z, off);
                    v.w += __shfl_xor_sync(0xffffffffu, v.w, off);
                }
                if (lane == 0) {
                    float al0 = sigf(v.x + alpha_b[0]);
                    float al1 = sigf(v.y + alpha_b[1]);
                    float hx0 = v.z + Whx_b[0];
                    float hx1 = v.w + Whx_b[1];
                    float xp0 = g_x[pn * BATCH * 2 + b * 2];
                    float xp1 = g_x[pn * BATCH * 2 + b * 2 + 1];
                    float tv = tau[(size_t)b * SEQ + (t - 1)];
                    float xm0 = (1.f + tv * MHU) * xp0 - (tv * MHU) * xp1;
                    float xm1 = tv * (1.f / MHU) * xp0 + xp1;
                    x0 = al0 * xm0 + (1.f - al0) * hx0;
                    x1 = al1 * xm1 + (1.f - al1) * hx1;
                }
            }
            if (lane == 0) {
                s_x[row] = make_float2(x0, x1);
                if (nblk == 0) {
                    g_x[p * BATCH * 2 + b * 2]     = x0;
                    g_x[p * BATCH * 2 + b * 2 + 1] = x1;
                    if (t > 0) {
                        float* prow = out + ((size_t)b * SEQ + (t - 1)) * ZS;
                        prow[0] = x0;
                        prow[1] = x1;
                    }
                }
            }
        }
    }
    __syncthreads();

    // ---------------- phase B: LSTM gates + dots ----------------
    const size_t A1 = (size_t)pn * BATCH * KW;
    const int parity = q & 1;
    const int jj = q >> 1;
    {
        float d0 = 0.f, d1 = 0.f, d2 = 0.f, d3 = 0.f;
        const int row_blk = warp_m * 16 + r + parity * 8;
        const int b = m0 + row_blk;
        const float2 xv = s_x[row_blk];
        #pragma unroll
        for (int j = 0; j < 2; j++) {
            float c0 = acc[j][0], c1 = acc[j][1], c2 = acc[j][2], c3 = acc[j][3];
            float p0 = __shfl_xor_sync(0xffffffffu, c0, 1);
            float p1 = __shfl_xor_sync(0xffffffffu, c1, 1);
            float p2 = __shfl_xor_sync(0xffffffffu, c2, 1);
            float p3 = __shfl_xor_sync(0xffffffffu, c3, 1);
            float gi, gf, gg, go;
            if (!parity) { gi = c0; gf = c1; gg = p0; go = p1; }
            else         { gi = p2; gf = p3; gg = c2; go = c3; }
            const int jgl = warp_n * 4 + j * 2 + jj;       // local hidden idx 0..31
            const int jg  = (n0 >> 2) + jgl;               // global hidden idx
            const int npl = 4 * jgl;
            float4 bv = *(const float4*)(g_bint + 4 * jg);
            gi += bv.x + xv.x * s_wx[npl + 0].x + xv.y * s_wx[npl + 0].y;
            gf += bv.y + xv.x * s_wx[npl + 1].x + xv.y * s_wx[npl + 1].y;
            gg += bv.z + xv.x * s_wx[npl + 2].x + xv.y * s_wx[npl + 2].y;
            go += bv.w + xv.x * s_wx[npl + 3].x + xv.y * s_wx[npl + 3].y;
            float co = g_c[b * HIDDEN + jg];
            float cn = sigf(gf) * co + sigf(gi) * tanhfast(gg);
            float h  = sigf(go) * tanhfast(cn);
            g_c[b * HIDDEN + jg] = cn;
            out[((size_t)b * SEQ + t) * ZS + 2 + jg] = h;
            __half hh, hl;
            h16split(h, &hh, &hl);
            g_Ahi[A1 + (size_t)b * KW + 128 + jg] = hh;
            g_Alo[A1 + (size_t)b * KW + 128 + jg] = hl;
            d0 += h * alpha_w[jg];
            d1 += h * alpha_w[HIDDEN + jg];
            d2 += h * Whx_w[jg];
            d3 += h * Whx_w[HIDDEN + jg];
        }
        d0 += __shfl_xor_sync(0xffffffffu, d0, 2);
        d1 += __shfl_xor_sync(0xffffffffu, d1, 2);
        d2 += __shfl_xor_sync(0xffffffffu, d2, 2);
        d3 += __shfl_xor_sync(0xffffffffu, d3, 2);
        if (q < 2) partsm[row_blk][warp_n] = make_float4(d0, d1, d2, d3);
    }
    __syncthreads();
    if (tid < 64) {
        float4 s = partsm[tid][0];
        #pragma unroll
        for (int w = 1; w < 8; w++) {
            float4 v = partsm[tid][w];
            s.x += v.x; s.y += v.y; s.z += v.z; s.w += v.w;
        }
        g_part[((size_t)(p * 4 + grp) * 64 + tid) * 32 + nblk] = s;
    }

    // stage u_{t+1}: this CTA covers 2 of the 64 rows (threads 0-255)
    if (t + 1 < SEQ && tid < 256) {
        int row = 2 * nblk + (tid >> 7);
        int col = tid & 127;
        int b = m0 + row;
        float u = rnn_input[((size_t)b * SEQ + (t + 1)) * INPUT + col];
        __half hi, lo;
        h16split(u, &hi, &lo);
        g_Ahi[A1 + (size_t)b * KW + col] = hi;
        g_Alo[A1 + (size_t)b * KW + col] = lo;
    }
}

// ---------------------------------------------------------------------------
__global__ void finalize(const float* __restrict__ tau,
                         const float* __restrict__ alpha_b, const float* __restrict__ Whx_b,
                         const float* __restrict__ c_z0, float* __restrict__ out) {
    int b = blockIdx.x, tid = threadIdx.x;
    __shared__ float2 s_xf;
    if (tid < 32) {
        const float4* pp = g_part + (size_t)(1 * 4 + (b >> 6)) * 64 * 32 + (size_t)(b & 63) * 32;
        float4 v = __ldcg(pp + tid);
        #pragma unroll
        for (int off = 16; off > 0; off >>= 1) {
            v.x += __shfl_xor_sync(0xffffffffu, v.x, off);
            v.y += __shfl_xor_sync(0xffffffffu, v.y, off);
            v.z += __shfl_xor_sync(0xffffffffu, v.z, off);
            v.w += __shfl_xor_sync(0xffffffffu, v.w, off);
        }
        if (tid == 0) {
            float al0 = sigf(v.x + alpha_b[0]);
            float al1 = sigf(v.y + alpha_b[1]);
            float hx0 = v.z + Whx_b[0];
            float hx1 = v.w + Whx_b[1];
            float xp0 = g_x[BATCH * 2 + b * 2];       // parity 1 = step 255
            float xp1 = g_x[BATCH * 2 + b * 2 + 1];
            float tv = tau[(size_t)b * SEQ + (SEQ - 1)];
            float xm0 = (1.f + tv * MHU) * xp0 - (tv * MHU) * xp1;
            float xm1 = tv * (1.f / MHU) * xp0 + xp1;
            float x0 = al0 * xm0 + (1.f - al0) * hx0;
            float x1 = al1 * xm1 + (1.f - al1) * hx1;
            float* prow = out + ((size_t)b * SEQ + (SEQ - 1)) * ZS;
            prow[0] = x0; prow[1] = x1;
            s_xf = make_float2(x0, x1);
        }
    }
    __syncthreads();
    size_t base = (size_t)BATCH * SEQ * ZS;
    float* zf  = out + base + (size_t)b * ZS;
    float* czf = out + base + (size_t)BATCH * ZS + (size_t)b * ZS;
    const float* last = out + ((size_t)b * SEQ + (SEQ - 1)) * ZS;
    for (int k = tid; k < ZS; k += 256) {
        zf[k]  = (k == 0) ? s_xf.x : (k == 1) ? s_xf.y : last[k];
        czf[k] = (k < 2) ? c_z0[b * ZS + k] : g_c[(size_t)b * HIDDEN + (k - 2)];
    }
}

// ---------------------------------------------------------------------------
extern "C" void kernel_launch(void* const* d_in, const int* in_sizes, int n_in,
                              void* d_out, int out_size) {
    const float* rnn_input = (const float*)d_in[0];
    const float* tau       = (const float*)d_in[1];
    const float* z0        = (const float*)d_in[2];
    const float* c_z0      = (const float*)d_in[3];
    const float* WU_w      = (const float*)d_in[4];
    const float* WU_b      = (const float*)d_in[5];
    const float* alpha_w   = (const float*)d_in[6];
    const float* alpha_b   = (const float*)d_in[7];
    const float* Whx_w     = (const float*)d_in[8];
    const float* Whx_b     = (const float*)d_in[9];
    float* out = (float*)d_out;

    static bool attr_set = false;
    if (!attr_set) {
        cudaFuncSetAttribute(step_kernel, cudaFuncAttributeMaxDynamicSharedMemorySize,
                             2 * STG_B);
        attr_set = true;
    }

    repack<<<4096, 256>>>(WU_w, WU_b);
    init_state<<<BATCH, 256>>>(z0, c_z0, rnn_input);
    for (int t = 0; t < SEQ; t++) {
        step_kernel<<<128, 1024, 2 * STG_B>>>(rnn_input, tau, alpha_w, alpha_b,
                                              Whx_w, Whx_b, out, t);
    }
    finalize<<<BATCH, 256>>>(tau, alpha_b, Whx_b, c_z0, out);
}